// round 11
// baseline (speedup 1.0000x reference)
#include <cuda_runtime.h>
#include <cuda_fp16.h>
#include <cstdint>

#define TOKS 8192
#define HDIM 1024
#define FDIM 4096
#define NEXP 8

// ---------------- scratch (__device__ globals; no allocation) ----------------
__device__ int    g_cnt[NEXP];
__device__ int    g_tok[NEXP * TOKS];
__device__ int    g_slot[NEXP * TOKS];
__device__ float  g_wt[NEXP * TOKS];
__device__ __half g_x16[(size_t)TOKS * HDIM];            // fp16 x (16 MB)
__device__ __half g_wg16[(size_t)NEXP * FDIM * HDIM];    // gate W, [e][n][k] (64 MB)
__device__ __half g_wu16[(size_t)NEXP * FDIM * HDIM];    // up   W, [e][n][k] (64 MB)
__device__ __half g_wd16[(size_t)NEXP * HDIM * FDIM];    // down W, [e][n][k] (64 MB)
__device__ __half g_h16[(size_t)2 * TOKS * FDIM];        // hidden (128 MB)
__device__ float  g_y[(size_t)2 * TOKS * HDIM];          // slot outputs (64 MB)

// ---------------- helpers ----------------
static __device__ __forceinline__ uint32_t smem_u32(const void* p) {
    uint32_t a;
    asm("{ .reg .u64 t; cvta.to.shared.u64 t, %1; cvt.u32.u64 %0, t; }" : "=r"(a) : "l"(p));
    return a;
}
static __device__ __forceinline__ void mma16(float* c, const uint32_t* a, const uint32_t* b) {
    asm volatile(
        "mma.sync.aligned.m16n8k16.row.col.f32.f16.f16.f32 "
        "{%0,%1,%2,%3}, {%4,%5,%6,%7}, {%8,%9}, {%0,%1,%2,%3};"
        : "+f"(c[0]), "+f"(c[1]), "+f"(c[2]), "+f"(c[3])
        : "r"(a[0]), "r"(a[1]), "r"(a[2]), "r"(a[3]), "r"(b[0]), "r"(b[1]));
}
#define LDSM4(r0, r1, r2, r3, addr)                                              \
    asm volatile("ldmatrix.sync.aligned.m8n8.x4.shared.b16 {%0,%1,%2,%3}, [%4];" \
                 : "=r"(r0), "=r"(r1), "=r"(r2), "=r"(r3) : "r"(addr))
#define CP16(dst, src, sz) \
    asm volatile("cp.async.cg.shared.global [%0], [%1], 16, %2;\n" ::"r"(dst), "l"(src), "r"(sz))
#define CP_COMMIT() asm volatile("cp.async.commit_group;\n" ::: "memory")
#define CP_WAITG1() asm volatile("cp.async.wait_group 1;\n" ::: "memory")
#define CP_WAIT0()  asm volatile("cp.async.wait_group 0;\n" ::: "memory")

static __device__ __forceinline__ float silu(float v) { return v / (1.f + __expf(-v)); }

static __device__ __forceinline__ int expert_off(int e) {
    int off = 0;
#pragma unroll
    for (int i = 0; i < NEXP; i++) if (i < e) off += g_cnt[i];
    return off;
}

// ---------------- convert x -> fp16 (also zeroes g_cnt) ----------------
__global__ void conv_x(const float* __restrict__ x) {
    if (blockIdx.x == 0 && threadIdx.x < NEXP) g_cnt[threadIdx.x] = 0;
    size_t i = ((size_t)blockIdx.x * 256 + threadIdx.x) * 8;
    float4 a = *reinterpret_cast<const float4*>(x + i);
    float4 b = *reinterpret_cast<const float4*>(x + i + 4);
    __half2 h[4];
    h[0] = __floats2half2_rn(a.x, a.y);
    h[1] = __floats2half2_rn(a.z, a.w);
    h[2] = __floats2half2_rn(b.x, b.y);
    h[3] = __floats2half2_rn(b.z, b.w);
    *reinterpret_cast<uint4*>(g_x16 + i) = *reinterpret_cast<uint4*>(h);
}

// ---------------- convert+transpose W: [e][k][n] fp32 -> [e][n][k] fp16 ----------------
__global__ void conv_w(const float* __restrict__ src, __half* __restrict__ dst,
                       int Kd, int Nd) {
    __shared__ float t[64][65];
    int e = blockIdx.z;
    int k0 = blockIdx.y * 64, n0 = blockIdx.x * 64;
    const float* S = src + ((size_t)e * Kd + k0) * Nd + n0;
    int tid = threadIdx.x;
    int kr = tid >> 4, nc = (tid & 15) * 4;
#pragma unroll
    for (int j = 0; j < 4; j++) {
        float4 v = *reinterpret_cast<const float4*>(S + (size_t)(kr + j * 16) * Nd + nc);
        t[kr + j * 16][nc + 0] = v.x;
        t[kr + j * 16][nc + 1] = v.y;
        t[kr + j * 16][nc + 2] = v.z;
        t[kr + j * 16][nc + 3] = v.w;
    }
    __syncthreads();
    int nr = tid >> 2, kc = (tid & 3) * 16;
    __half hb[16];
#pragma unroll
    for (int q = 0; q < 16; q++) hb[q] = __float2half_rn(t[kc + q][nr]);
    __half* D = dst + ((size_t)e * Nd + n0 + nr) * Kd + k0 + kc;
    *reinterpret_cast<uint4*>(D)     = *reinterpret_cast<uint4*>(hb);
    *reinterpret_cast<uint4*>(D + 8) = *reinterpret_cast<uint4*>(hb + 8);
}

// ---------------- router ----------------
__global__ void moe_router(const float* __restrict__ x, const float* __restrict__ wg,
                           float* __restrict__ logits_out) {
    int t = blockIdx.x * 8 + (threadIdx.x >> 5);
    int lane = threadIdx.x & 31;
    const float* xr = x + (size_t)t * HDIM;
    float acc[8] = {0.f, 0.f, 0.f, 0.f, 0.f, 0.f, 0.f, 0.f};
    for (int j = lane; j < HDIM; j += 32) {
        float xv = xr[j];
        const float4* w4 = reinterpret_cast<const float4*>(wg + (size_t)j * NEXP);
        float4 a = w4[0], b = w4[1];
        acc[0] += xv * a.x; acc[1] += xv * a.y; acc[2] += xv * a.z; acc[3] += xv * a.w;
        acc[4] += xv * b.x; acc[5] += xv * b.y; acc[6] += xv * b.z; acc[7] += xv * b.w;
    }
#pragma unroll
    for (int o = 16; o > 0; o >>= 1)
#pragma unroll
        for (int k = 0; k < 8; k++) acc[k] += __shfl_xor_sync(0xffffffffu, acc[k], o);

    if (lane == 0) {
#pragma unroll
        for (int k = 0; k < 8; k++) logits_out[(size_t)t * NEXP + k] = acc[k];
        int i0 = 0; float v0 = acc[0];
#pragma unroll
        for (int k = 1; k < 8; k++) if (acc[k] > v0) { v0 = acc[k]; i0 = k; }
        int i1 = -1; float v1 = -3.4e38f;
#pragma unroll
        for (int k = 0; k < 8; k++) if (k != i0 && acc[k] > v1) { v1 = acc[k]; i1 = k; }
        float w0 = 1.f / (1.f + __expf(v1 - v0));
        float w1 = 1.f - w0;
        int p0 = atomicAdd(&g_cnt[i0], 1);
        g_tok[i0 * TOKS + p0] = t; g_slot[i0 * TOKS + p0] = 0; g_wt[i0 * TOKS + p0] = w0;
        int p1 = atomicAdd(&g_cnt[i1], 1);
        g_tok[i1 * TOKS + p1] = t; g_slot[i1 * TOKS + p1] = 1; g_wt[i1 * TOKS + p1] = w1;
    }
}

// ---------------- fused gate+up GEMM (BM=256, 512 thr, BK=64, 3-stage) ----------------
// BM=256, BN=64 per side. Pitch 72 halves (144 B). Stage: A 256*144=36864B,
// Bg 64*144=9216B, Bu 9216B -> 55296B. 3 stages = 165888B. 1 CTA/SM, 128 regs/thr.
__global__ void __launch_bounds__(512, 1)
moe_gateup() {
    int e = blockIdx.z;
    int cnt = g_cnt[e];
    int base = blockIdx.y * 256;
    if (base >= cnt) return;
    int n0 = blockIdx.x * 64;
    int off = expert_off(e);
    const __half* wge = g_wg16 + (size_t)e * FDIM * HDIM;
    const __half* wue = g_wu16 + (size_t)e * FDIM * HDIM;

    extern __shared__ char smem8[];
    uint32_t su = smem_u32(smem8);
    const uint32_t STG = 55296;
    const uint32_t BGO = 36864, BUO = 46080;

    int tid = threadIdx.x, lane = tid & 31;
    int gid = lane >> 2, tig = lane & 3;
    int wid = tid >> 5;           // 0..15
    int wm = wid >> 2, wn = wid & 3;   // wm 0..3 (64 rows each), wn 0..3 (16 n each)

    // cp.async descriptors: A 256 rows x 8 chunks = 2048 -> 4/thread
    const __half* asrc[4]; uint32_t asz[4], adst[4];
#pragma unroll
    for (int j = 0; j < 4; j++) {
        int idx = tid + j * 512;
        int row = idx >> 3, c = idx & 7;
        int r = base + row;
        bool v = r < cnt;
        int tok = v ? g_tok[e * TOKS + r] : 0;
        asrc[j] = g_x16 + (size_t)tok * HDIM + c * 8;
        asz[j] = v ? 16u : 0u;
        adst[j] = (uint32_t)(row * 144 + c * 16);
    }
    // B per side: 64 rows x 8 chunks = 512 -> 1/thread
    int bn = tid >> 3, bc = tid & 7;
    const __half* gsrc = wge + (size_t)(n0 + bn) * HDIM + bc * 8;
    const __half* usrc = wue + (size_t)(n0 + bn) * HDIM + bc * 8;
    uint32_t bdst = (uint32_t)(bn * 144 + bc * 16);

    // ldmatrix per-lane byte offsets (within a stage), pitch 72 halves
    uint32_t aoff[4];
#pragma unroll
    for (int m = 0; m < 4; m++)
        aoff[m] = (uint32_t)(((wm * 64 + m * 16 + (lane & 15)) * 72 + (lane >> 4) * 8) * 2);
    uint32_t boff = (uint32_t)(((wn * 16 + (lane & 7) + ((lane >> 4) & 1) * 8) * 72 +
                                ((lane >> 3) & 1) * 8) * 2);

    float accG[4][2][4], accU[4][2][4];
#pragma unroll
    for (int m = 0; m < 4; m++)
#pragma unroll
        for (int n = 0; n < 2; n++)
#pragma unroll
            for (int q = 0; q < 4; q++) { accG[m][n][q] = 0.f; accU[m][n][q] = 0.f; }

    const int KI = HDIM / 64;  // 16

#define GU_ISSUE(s, k0)                                                  \
    do {                                                                 \
        uint32_t ab = su + (uint32_t)(s) * STG;                          \
        _Pragma("unroll") for (int j = 0; j < 4; j++)                    \
            CP16(ab + adst[j], asrc[j] + (k0), asz[j]);                  \
        CP16(ab + BGO + bdst, gsrc + (k0), 16u);                         \
        CP16(ab + BUO + bdst, usrc + (k0), 16u);                         \
        CP_COMMIT();                                                     \
    } while (0)

    GU_ISSUE(0, 0);
    GU_ISSUE(1, 64);

    int sC = 0, sP = 2;
    for (int i = 0; i < KI; i++) {
        if (i + 1 < KI) CP_WAITG1(); else CP_WAIT0();
        __syncthreads();
        if (i + 2 < KI) {
            GU_ISSUE(sP, (i + 2) * 64);
            sP = (sP == 2) ? 0 : sP + 1;
        }
        uint32_t ab = su + (uint32_t)sC * STG;
        sC = (sC == 2) ? 0 : sC + 1;
#pragma unroll
        for (int kk = 0; kk < 4; kk++) {
            uint32_t kb = (uint32_t)(kk * 32);  // 16 halves per k-step
            uint32_t af[4][4], bg[4], bu[4];
#pragma unroll
            for (int m = 0; m < 4; m++)
                LDSM4(af[m][0], af[m][1], af[m][2], af[m][3], ab + aoff[m] + kb);
            LDSM4(bg[0], bg[1], bg[2], bg[3], ab + BGO + boff + kb);
            LDSM4(bu[0], bu[1], bu[2], bu[3], ab + BUO + boff + kb);
#pragma unroll
            for (int m = 0; m < 4; m++)
#pragma unroll
                for (int n = 0; n < 2; n++) {
                    mma16(accG[m][n], af[m], bg + n * 2);
                    mma16(accU[m][n], af[m], bu + n * 2);
                }
        }
    }
#undef GU_ISSUE

    // epilogue: g_h16 = fp16(silu(g) * u)
#pragma unroll
    for (int m = 0; m < 4; m++) {
#pragma unroll
        for (int half = 0; half < 2; half++) {
            int R = wm * 64 + m * 16 + gid + half * 8;
            int r = base + R;
            if (r >= cnt) continue;
            size_t rb = (size_t)(off + r) * FDIM + n0;
#pragma unroll
            for (int n = 0; n < 2; n++) {
                int col = wn * 16 + n * 8 + 2 * tig;
                float h0 = silu(accG[m][n][half * 2 + 0]) * accU[m][n][half * 2 + 0];
                float h1 = silu(accG[m][n][half * 2 + 1]) * accU[m][n][half * 2 + 1];
                *reinterpret_cast<__half2*>(g_h16 + rb + col) = __floats2half2_rn(h0, h1);
            }
        }
    }
}

// ---------------- down GEMM (BM=256, 512 thr, BN=128, BK=64, 3-stage) ----------------
// Stage: A 256*144=36864B + B 128*144=18432B = 55296B. 3 stages = 165888B.
__global__ void __launch_bounds__(512, 1)
moe_down() {
    int e = blockIdx.z;
    int cnt = g_cnt[e];
    int base = blockIdx.y * 256;
    if (base >= cnt) return;
    int n0 = blockIdx.x * 128;
    int off = expert_off(e);
    const __half* wde = g_wd16 + (size_t)e * HDIM * FDIM;

    extern __shared__ char smem8[];
    uint32_t su = smem_u32(smem8);
    const uint32_t STG = 55296;
    const uint32_t BO = 36864;

    int tid = threadIdx.x, lane = tid & 31;
    int gid = lane >> 2, tig = lane & 3;
    int wid = tid >> 5;
    int wm = wid >> 2, wn = wid & 3;   // warp tile 64m x 32n

    const __half* asrc[4]; uint32_t asz[4], adst[4];
#pragma unroll
    for (int j = 0; j < 4; j++) {
        int idx = tid + j * 512;
        int row = idx >> 3, c = idx & 7;
        int r = base + row;
        bool v = r < cnt;
        size_t arow = v ? (size_t)(off + r) : 0;
        asrc[j] = g_h16 + arow * FDIM + c * 8;
        asz[j] = v ? 16u : 0u;
        adst[j] = (uint32_t)(row * 144 + c * 16);
    }
    // B: 128 rows x 8 chunks = 1024 -> 2/thread
    const __half* bsrc[2]; uint32_t bdst[2];
#pragma unroll
    for (int j = 0; j < 2; j++) {
        int idx = tid + j * 512;
        int n = idx >> 3, c = idx & 7;
        bsrc[j] = wde + (size_t)(n0 + n) * FDIM + c * 8;
        bdst[j] = (uint32_t)(n * 144 + c * 16);
    }

    uint32_t aoff[4];
#pragma unroll
    for (int m = 0; m < 4; m++)
        aoff[m] = (uint32_t)(((wm * 64 + m * 16 + (lane & 15)) * 72 + (lane >> 4) * 8) * 2);
    uint32_t boff[2];
#pragma unroll
    for (int p = 0; p < 2; p++)
        boff[p] = (uint32_t)(((wn * 32 + p * 16 + (lane & 7) + ((lane >> 4) & 1) * 8) * 72 +
                              ((lane >> 3) & 1) * 8) * 2);

    float acc[4][4][4];
#pragma unroll
    for (int m = 0; m < 4; m++)
#pragma unroll
        for (int n = 0; n < 4; n++)
#pragma unroll
            for (int q = 0; q < 4; q++) acc[m][n][q] = 0.f;

    const int KI = FDIM / 64;  // 64

#define DN_ISSUE(s, k0)                                                  \
    do {                                                                 \
        uint32_t ab = su + (uint32_t)(s) * STG;                          \
        _Pragma("unroll") for (int j = 0; j < 4; j++)                    \
            CP16(ab + adst[j], asrc[j] + (k0), asz[j]);                  \
        _Pragma("unroll") for (int j = 0; j < 2; j++)                    \
            CP16(ab + BO + bdst[j], bsrc[j] + (k0), 16u);                \
        CP_COMMIT();                                                     \
    } while (0)

    DN_ISSUE(0, 0);
    DN_ISSUE(1, 64);

    int sC = 0, sP = 2;
    for (int i = 0; i < KI; i++) {
        if (i + 1 < KI) CP_WAITG1(); else CP_WAIT0();
        __syncthreads();
        if (i + 2 < KI) {
            DN_ISSUE(sP, (i + 2) * 64);
            sP = (sP == 2) ? 0 : sP + 1;
        }
        uint32_t ab = su + (uint32_t)sC * STG;
        sC = (sC == 2) ? 0 : sC + 1;
#pragma unroll
        for (int kk = 0; kk < 4; kk++) {
            uint32_t kb = (uint32_t)(kk * 32);
            uint32_t af[4][4], bf[2][4];
#pragma unroll
            for (int m = 0; m < 4; m++)
                LDSM4(af[m][0], af[m][1], af[m][2], af[m][3], ab + aoff[m] + kb);
#pragma unroll
            for (int p = 0; p < 2; p++)
                LDSM4(bf[p][0], bf[p][1], bf[p][2], bf[p][3], ab + BO + boff[p] + kb);
#pragma unroll
            for (int m = 0; m < 4; m++)
#pragma unroll
                for (int n = 0; n < 4; n++)
                    mma16(acc[m][n], af[m], bf[n >> 1] + (n & 1) * 2);
        }
    }
#undef DN_ISSUE

    // epilogue: weighted scatter
#pragma unroll
    for (int m = 0; m < 4; m++) {
#pragma unroll
        for (int half = 0; half < 2; half++) {
            int R = wm * 64 + m * 16 + gid + half * 8;
            int r = base + R;
            if (r >= cnt) continue;
            int t = g_tok[e * TOKS + r];
            int sl = g_slot[e * TOKS + r];
            float w = g_wt[e * TOKS + r];
            size_t yb = ((size_t)sl * TOKS + t) * HDIM + n0;
#pragma unroll
            for (int n = 0; n < 4; n++) {
                int col = wn * 32 + n * 8 + 2 * tig;
                float v0 = acc[m][n][half * 2 + 0], v1 = acc[m][n][half * 2 + 1];
                *reinterpret_cast<float2*>(g_y + yb + col) = make_float2(w * v0, w * v1);
            }
        }
    }
}

// ---------------- combine: out = y[slot0] + y[slot1] ----------------
__global__ void moe_combine(float* __restrict__ out) {
    size_t i = (size_t)blockIdx.x * 256 + threadIdx.x;
    const float4* y0 = reinterpret_cast<const float4*>(g_y);
    const float4* y1 = y0 + (size_t)TOKS * HDIM / 4;
    float4 a = y0[i], b = y1[i];
    reinterpret_cast<float4*>(out)[i] = make_float4(a.x + b.x, a.y + b.y, a.z + b.z, a.w + b.w);
}

// ---------------- launch ----------------
extern "C" void kernel_launch(void* const* d_in, const int* in_sizes, int n_in,
                              void* d_out, int out_size) {
    const float* x   = (const float*)d_in[0];
    const float* wg  = (const float*)d_in[1];
    const float* wgp = (const float*)d_in[2];
    const float* wup = (const float*)d_in[3];
    const float* wdp = (const float*)d_in[4];
    float* out = (float*)d_out;

    cudaFuncSetAttribute(moe_gateup, cudaFuncAttributeMaxDynamicSharedMemorySize, 165888);
    cudaFuncSetAttribute(moe_down,   cudaFuncAttributeMaxDynamicSharedMemorySize, 165888);

    conv_x<<<(TOKS * HDIM / 8) / 256, 256>>>(x);                 // #0 (also zeroes g_cnt)
    {
        __half* dwg; cudaGetSymbolAddress((void**)&dwg, g_wg16);
        __half* dwu; cudaGetSymbolAddress((void**)&dwu, g_wu16);
        __half* dwd; cudaGetSymbolAddress((void**)&dwd, g_wd16);
        conv_w<<<dim3(FDIM / 64, HDIM / 64, NEXP), 256>>>(wgp, dwg, HDIM, FDIM);  // #1
        conv_w<<<dim3(FDIM / 64, HDIM / 64, NEXP), 256>>>(wup, dwu, HDIM, FDIM);  // #2
        conv_w<<<dim3(HDIM / 64, FDIM / 64, NEXP), 256>>>(wdp, dwd, FDIM, HDIM);  // #3
    }
    moe_router<<<TOKS / 8, 256>>>(x, wg, out + (size_t)TOKS * HDIM);              // #4
    moe_gateup<<<dim3(FDIM / 64, 16, NEXP), 512, 165888>>>();                     // #5
    moe_down<<<dim3(HDIM / 128, 16, NEXP), 512, 165888>>>();                      // #6
    moe_combine<<<(TOKS * HDIM / 4) / 256, 256>>>(out);                           // #7
}

// round 12
// speedup vs baseline: 1.1019x; 1.1019x over previous
#include <cuda_runtime.h>
#include <cuda_fp16.h>
#include <cstdint>

#define TOKS 8192
#define HDIM 1024
#define FDIM 4096
#define NEXP 8

// ---------------- scratch (__device__ globals; no allocation) ----------------
__device__ int    g_cnt[NEXP];
__device__ int    g_tok[NEXP * TOKS];
__device__ int    g_slot[NEXP * TOKS];
__device__ float  g_wt[NEXP * TOKS];
__device__ __half g_x16[(size_t)TOKS * HDIM];            // fp16 x (16 MB)
__device__ __half g_wg16[(size_t)NEXP * FDIM * HDIM];    // gate W, [e][n][k] (64 MB)
__device__ __half g_wu16[(size_t)NEXP * FDIM * HDIM];    // up   W, [e][n][k] (64 MB)
__device__ __half g_wd16[(size_t)NEXP * HDIM * FDIM];    // down W, [e][n][k] (64 MB)
__device__ __half g_h16[(size_t)2 * TOKS * FDIM];        // hidden (128 MB)
__device__ float  g_y[(size_t)2 * TOKS * HDIM];          // slot outputs (64 MB)

// ---------------- helpers ----------------
static __device__ __forceinline__ uint32_t smem_u32(const void* p) {
    uint32_t a;
    asm("{ .reg .u64 t; cvta.to.shared.u64 t, %1; cvt.u32.u64 %0, t; }" : "=r"(a) : "l"(p));
    return a;
}
static __device__ __forceinline__ void mma16(float* c, const uint32_t* a, const uint32_t* b) {
    asm volatile(
        "mma.sync.aligned.m16n8k16.row.col.f32.f16.f16.f32 "
        "{%0,%1,%2,%3}, {%4,%5,%6,%7}, {%8,%9}, {%0,%1,%2,%3};"
        : "+f"(c[0]), "+f"(c[1]), "+f"(c[2]), "+f"(c[3])
        : "r"(a[0]), "r"(a[1]), "r"(a[2]), "r"(a[3]), "r"(b[0]), "r"(b[1]));
}
#define LDSM4(r0, r1, r2, r3, addr)                                              \
    asm volatile("ldmatrix.sync.aligned.m8n8.x4.shared.b16 {%0,%1,%2,%3}, [%4];" \
                 : "=r"(r0), "=r"(r1), "=r"(r2), "=r"(r3) : "r"(addr))
#define CP16(dst, src, sz) \
    asm volatile("cp.async.cg.shared.global [%0], [%1], 16, %2;\n" ::"r"(dst), "l"(src), "r"(sz))
#define CP_COMMIT() asm volatile("cp.async.commit_group;\n" ::: "memory")
#define CP_WAITG1() asm volatile("cp.async.wait_group 1;\n" ::: "memory")
#define CP_WAIT0()  asm volatile("cp.async.wait_group 0;\n" ::: "memory")

static __device__ __forceinline__ float silu(float v) { return v / (1.f + __expf(-v)); }

static __device__ __forceinline__ int expert_off(int e) {
    int off = 0;
#pragma unroll
    for (int i = 0; i < NEXP; i++) if (i < e) off += g_cnt[i];
    return off;
}

// ---------------- convert x -> fp16 (also zeroes g_cnt) ----------------
__global__ void conv_x(const float* __restrict__ x) {
    if (blockIdx.x == 0 && threadIdx.x < NEXP) g_cnt[threadIdx.x] = 0;
    size_t i = ((size_t)blockIdx.x * 256 + threadIdx.x) * 8;
    float4 a = *reinterpret_cast<const float4*>(x + i);
    float4 b = *reinterpret_cast<const float4*>(x + i + 4);
    __half2 h[4];
    h[0] = __floats2half2_rn(a.x, a.y);
    h[1] = __floats2half2_rn(a.z, a.w);
    h[2] = __floats2half2_rn(b.x, b.y);
    h[3] = __floats2half2_rn(b.z, b.w);
    *reinterpret_cast<uint4*>(g_x16 + i) = *reinterpret_cast<uint4*>(h);
}

// ---------------- convert+transpose ALL W: [e][k][n] fp32 -> [e][n][k] fp16 ----------------
// One launch for the 3 weight sets: grid (64, 16, 24); set = z>>3, e = z&7.
// dst symbols referenced in device code (device addresses, not host shadows).
__global__ void conv_w3(const float* __restrict__ wgp, const float* __restrict__ wup,
                        const float* __restrict__ wdp) {
    __shared__ float t[64][65];
    int set = blockIdx.z >> 3, e = blockIdx.z & 7;
    const float* src; __half* dst; int Kd, Nd, k0, n0;
    if (set == 0)      { src = wgp; dst = g_wg16; Kd = HDIM; Nd = FDIM; }
    else if (set == 1) { src = wup; dst = g_wu16; Kd = HDIM; Nd = FDIM; }
    else               { src = wdp; dst = g_wd16; Kd = FDIM; Nd = HDIM; }
    if (set < 2) { k0 = blockIdx.y * 64; n0 = blockIdx.x * 64; }   // K tiles 16, N tiles 64
    else         { k0 = blockIdx.x * 64; n0 = blockIdx.y * 64; }   // K tiles 64, N tiles 16

    const float* S = src + ((size_t)e * Kd + k0) * Nd + n0;
    int tid = threadIdx.x;
    int kr = tid >> 4, nc = (tid & 15) * 4;
#pragma unroll
    for (int j = 0; j < 4; j++) {
        float4 v = *reinterpret_cast<const float4*>(S + (size_t)(kr + j * 16) * Nd + nc);
        t[kr + j * 16][nc + 0] = v.x;
        t[kr + j * 16][nc + 1] = v.y;
        t[kr + j * 16][nc + 2] = v.z;
        t[kr + j * 16][nc + 3] = v.w;
    }
    __syncthreads();
    int nr = tid >> 2, kc = (tid & 3) * 16;
    __half hb[16];
#pragma unroll
    for (int q = 0; q < 16; q++) hb[q] = __float2half_rn(t[kc + q][nr]);
    __half* D = dst + ((size_t)e * Nd + n0 + nr) * Kd + k0 + kc;
    *reinterpret_cast<uint4*>(D)     = *reinterpret_cast<uint4*>(hb);
    *reinterpret_cast<uint4*>(D + 8) = *reinterpret_cast<uint4*>(hb + 8);
}

// ---------------- router ----------------
__global__ void moe_router(const float* __restrict__ x, const float* __restrict__ wg,
                           float* __restrict__ logits_out) {
    int t = blockIdx.x * 8 + (threadIdx.x >> 5);
    int lane = threadIdx.x & 31;
    const float* xr = x + (size_t)t * HDIM;
    float acc[8] = {0.f, 0.f, 0.f, 0.f, 0.f, 0.f, 0.f, 0.f};
    for (int j = lane; j < HDIM; j += 32) {
        float xv = xr[j];
        const float4* w4 = reinterpret_cast<const float4*>(wg + (size_t)j * NEXP);
        float4 a = w4[0], b = w4[1];
        acc[0] += xv * a.x; acc[1] += xv * a.y; acc[2] += xv * a.z; acc[3] += xv * a.w;
        acc[4] += xv * b.x; acc[5] += xv * b.y; acc[6] += xv * b.z; acc[7] += xv * b.w;
    }
#pragma unroll
    for (int o = 16; o > 0; o >>= 1)
#pragma unroll
        for (int k = 0; k < 8; k++) acc[k] += __shfl_xor_sync(0xffffffffu, acc[k], o);

    if (lane == 0) {
#pragma unroll
        for (int k = 0; k < 8; k++) logits_out[(size_t)t * NEXP + k] = acc[k];
        int i0 = 0; float v0 = acc[0];
#pragma unroll
        for (int k = 1; k < 8; k++) if (acc[k] > v0) { v0 = acc[k]; i0 = k; }
        int i1 = -1; float v1 = -3.4e38f;
#pragma unroll
        for (int k = 0; k < 8; k++) if (k != i0 && acc[k] > v1) { v1 = acc[k]; i1 = k; }
        float w0 = 1.f / (1.f + __expf(v1 - v0));
        float w1 = 1.f - w0;
        int p0 = atomicAdd(&g_cnt[i0], 1);
        g_tok[i0 * TOKS + p0] = t; g_slot[i0 * TOKS + p0] = 0; g_wt[i0 * TOKS + p0] = w0;
        int p1 = atomicAdd(&g_cnt[i1], 1);
        g_tok[i1 * TOKS + p1] = t; g_slot[i1 * TOKS + p1] = 1; g_wt[i1 * TOKS + p1] = w1;
    }
}

// ---------------- fused gate+up GEMM (fp16, ldmatrix, BK=64, 3-stage) — R9 config ----------------
// BM=128, BN=64 per side, BK=64, pitch 72 halves (144 B).
// Stage: A 128*144=18432B, Bg 64*144=9216B, Bu 9216B -> 36864B. 3 stages = 110592B. 2 CTAs/SM.
__global__ void __launch_bounds__(256, 2)
moe_gateup() {
    int e = blockIdx.z;
    int cnt = g_cnt[e];
    int base = blockIdx.y * 128;
    if (base >= cnt) return;
    int n0 = blockIdx.x * 64;
    int off = expert_off(e);
    const __half* wge = g_wg16 + (size_t)e * FDIM * HDIM;
    const __half* wue = g_wu16 + (size_t)e * FDIM * HDIM;

    extern __shared__ char smem8[];
    uint32_t su = smem_u32(smem8);
    const uint32_t STG = 36864;

    int tid = threadIdx.x, lane = tid & 31;
    int gid = lane >> 2, tig = lane & 3;
    int wid = tid >> 5, wm = wid >> 2, wn = wid & 3;

    // cp.async descriptors: A 128 rows x 8 chunks -> 4/thread
    const __half* asrc[4]; uint32_t asz[4], adst[4];
#pragma unroll
    for (int j = 0; j < 4; j++) {
        int idx = tid + j * 256;
        int row = idx >> 3, c = idx & 7;
        int r = base + row;
        bool v = r < cnt;
        int tok = v ? g_tok[e * TOKS + r] : 0;
        asrc[j] = g_x16 + (size_t)tok * HDIM + c * 8;
        asz[j] = v ? 16u : 0u;
        adst[j] = (uint32_t)(row * 144 + c * 16);
    }
    // B per side: 64 rows x 8 chunks -> 2/thread
    const __half* gsrc[2]; const __half* usrc[2]; uint32_t bdst[2];
#pragma unroll
    for (int j = 0; j < 2; j++) {
        int idx = tid + j * 256;
        int n = idx >> 3, c = idx & 7;
        gsrc[j] = wge + (size_t)(n0 + n) * HDIM + c * 8;
        usrc[j] = wue + (size_t)(n0 + n) * HDIM + c * 8;
        bdst[j] = (uint32_t)(n * 144 + c * 16);
    }

    // ldmatrix per-lane byte offsets (within a stage), pitch 72 halves
    uint32_t aoff[4];
#pragma unroll
    for (int m = 0; m < 4; m++)
        aoff[m] = (uint32_t)(((wm * 64 + m * 16 + (lane & 15)) * 72 + (lane >> 4) * 8) * 2);
    uint32_t boff = (uint32_t)(((wn * 16 + (lane & 7) + ((lane >> 4) & 1) * 8) * 72 +
                                ((lane >> 3) & 1) * 8) * 2);

    float accG[4][2][4], accU[4][2][4];
#pragma unroll
    for (int m = 0; m < 4; m++)
#pragma unroll
        for (int n = 0; n < 2; n++)
#pragma unroll
            for (int q = 0; q < 4; q++) { accG[m][n][q] = 0.f; accU[m][n][q] = 0.f; }

    const int KI = HDIM / 64;  // 16

#define GU_ISSUE(s, k0)                                                  \
    do {                                                                 \
        uint32_t ab = su + (uint32_t)(s) * STG;                          \
        _Pragma("unroll") for (int j = 0; j < 4; j++)                    \
            CP16(ab + adst[j], asrc[j] + (k0), asz[j]);                  \
        _Pragma("unroll") for (int j = 0; j < 2; j++)                    \
            CP16(ab + 18432u + bdst[j], gsrc[j] + (k0), 16u);            \
        _Pragma("unroll") for (int j = 0; j < 2; j++)                    \
            CP16(ab + 27648u + bdst[j], usrc[j] + (k0), 16u);            \
        CP_COMMIT();                                                     \
    } while (0)

    GU_ISSUE(0, 0);
    GU_ISSUE(1, 64);

    int sC = 0, sP = 2;
    for (int i = 0; i < KI; i++) {
        if (i + 1 < KI) CP_WAITG1(); else CP_WAIT0();
        __syncthreads();
        if (i + 2 < KI) {
            GU_ISSUE(sP, (i + 2) * 64);
            sP = (sP == 2) ? 0 : sP + 1;
        }
        uint32_t ab = su + (uint32_t)sC * STG;
        sC = (sC == 2) ? 0 : sC + 1;
#pragma unroll
        for (int kk = 0; kk < 4; kk++) {
            uint32_t kb = (uint32_t)(kk * 32);  // 16 halves per k-step
            uint32_t af[4][4], bg[4], bu[4];
#pragma unroll
            for (int m = 0; m < 4; m++)
                LDSM4(af[m][0], af[m][1], af[m][2], af[m][3], ab + aoff[m] + kb);
            LDSM4(bg[0], bg[1], bg[2], bg[3], ab + 18432u + boff + kb);
            LDSM4(bu[0], bu[1], bu[2], bu[3], ab + 27648u + boff + kb);
#pragma unroll
            for (int m = 0; m < 4; m++)
#pragma unroll
                for (int n = 0; n < 2; n++) {
                    mma16(accG[m][n], af[m], bg + n * 2);
                    mma16(accU[m][n], af[m], bu + n * 2);
                }
        }
    }
#undef GU_ISSUE

    // epilogue: g_h16 = fp16(silu(g) * u)
#pragma unroll
    for (int m = 0; m < 4; m++) {
#pragma unroll
        for (int half = 0; half < 2; half++) {
            int R = wm * 64 + m * 16 + gid + half * 8;
            int r = base + R;
            if (r >= cnt) continue;
            size_t rb = (size_t)(off + r) * FDIM + n0;
#pragma unroll
            for (int n = 0; n < 2; n++) {
                int col = wn * 16 + n * 8 + 2 * tig;
                float h0 = silu(accG[m][n][half * 2 + 0]) * accU[m][n][half * 2 + 0];
                float h1 = silu(accG[m][n][half * 2 + 1]) * accU[m][n][half * 2 + 1];
                *reinterpret_cast<__half2*>(g_h16 + rb + col) = __floats2half2_rn(h0, h1);
            }
        }
    }
}

// ---------------- down GEMM: y[slot][tok] = w * (g_h16 @ Wd), BK=64, 3-stage — R9 config ----------------
// Stage: A 18432B + B 128*144=18432B = 36864B. 3 stages = 110592B. 2 CTAs/SM.
__global__ void __launch_bounds__(256, 2)
moe_down() {
    int e = blockIdx.z;
    int cnt = g_cnt[e];
    int base = blockIdx.y * 128;
    if (base >= cnt) return;
    int n0 = blockIdx.x * 128;
    int off = expert_off(e);
    const __half* wde = g_wd16 + (size_t)e * HDIM * FDIM;

    extern __shared__ char smem8[];
    uint32_t su = smem_u32(smem8);
    const uint32_t STG = 36864;

    int tid = threadIdx.x, lane = tid & 31;
    int gid = lane >> 2, tig = lane & 3;
    int wid = tid >> 5, wm = wid >> 2, wn = wid & 3;

    const __half* asrc[4]; uint32_t asz[4], adst[4];
#pragma unroll
    for (int j = 0; j < 4; j++) {
        int idx = tid + j * 256;
        int row = idx >> 3, c = idx & 7;
        int r = base + row;
        bool v = r < cnt;
        size_t arow = v ? (size_t)(off + r) : 0;
        asrc[j] = g_h16 + arow * FDIM + c * 8;
        asz[j] = v ? 16u : 0u;
        adst[j] = (uint32_t)(row * 144 + c * 16);
    }
    const __half* bsrc[4]; uint32_t bdst[4];
#pragma unroll
    for (int j = 0; j < 4; j++) {
        int idx = tid + j * 256;
        int n = idx >> 3, c = idx & 7;
        bsrc[j] = wde + (size_t)(n0 + n) * FDIM + c * 8;
        bdst[j] = (uint32_t)(n * 144 + c * 16);
    }

    uint32_t aoff[4];
#pragma unroll
    for (int m = 0; m < 4; m++)
        aoff[m] = (uint32_t)(((wm * 64 + m * 16 + (lane & 15)) * 72 + (lane >> 4) * 8) * 2);
    uint32_t boff[2];
#pragma unroll
    for (int p = 0; p < 2; p++)
        boff[p] = (uint32_t)(((wn * 32 + p * 16 + (lane & 7) + ((lane >> 4) & 1) * 8) * 72 +
                              ((lane >> 3) & 1) * 8) * 2);

    float acc[4][4][4];
#pragma unroll
    for (int m = 0; m < 4; m++)
#pragma unroll
        for (int n = 0; n < 4; n++)
#pragma unroll
            for (int q = 0; q < 4; q++) acc[m][n][q] = 0.f;

    const int KI = FDIM / 64;  // 64

#define DN_ISSUE(s, k0)                                                  \
    do {                                                                 \
        uint32_t ab = su + (uint32_t)(s) * STG;                          \
        _Pragma("unroll") for (int j = 0; j < 4; j++)                    \
            CP16(ab + adst[j], asrc[j] + (k0), asz[j]);                  \
        _Pragma("unroll") for (int j = 0; j < 4; j++)                    \
            CP16(ab + 18432u + bdst[j], bsrc[j] + (k0), 16u);            \
        CP_COMMIT();                                                     \
    } while (0)

    DN_ISSUE(0, 0);
    DN_ISSUE(1, 64);

    int sC = 0, sP = 2;
    for (int i = 0; i < KI; i++) {
        if (i + 1 < KI) CP_WAITG1(); else CP_WAIT0();
        __syncthreads();
        if (i + 2 < KI) {
            DN_ISSUE(sP, (i + 2) * 64);
            sP = (sP == 2) ? 0 : sP + 1;
        }
        uint32_t ab = su + (uint32_t)sC * STG;
        sC = (sC == 2) ? 0 : sC + 1;
#pragma unroll
        for (int kk = 0; kk < 4; kk++) {
            uint32_t kb = (uint32_t)(kk * 32);
            uint32_t af[4][4], bf[2][4];
#pragma unroll
            for (int m = 0; m < 4; m++)
                LDSM4(af[m][0], af[m][1], af[m][2], af[m][3], ab + aoff[m] + kb);
#pragma unroll
            for (int p = 0; p < 2; p++)
                LDSM4(bf[p][0], bf[p][1], bf[p][2], bf[p][3], ab + 18432u + boff[p] + kb);
#pragma unroll
            for (int m = 0; m < 4; m++)
#pragma unroll
                for (int n = 0; n < 4; n++)
                    mma16(acc[m][n], af[m], bf[n >> 1] + (n & 1) * 2);
        }
    }
#undef DN_ISSUE

    // epilogue: weighted scatter
#pragma unroll
    for (int m = 0; m < 4; m++) {
#pragma unroll
        for (int half = 0; half < 2; half++) {
            int R = wm * 64 + m * 16 + gid + half * 8;
            int r = base + R;
            if (r >= cnt) continue;
            int t = g_tok[e * TOKS + r];
            int sl = g_slot[e * TOKS + r];
            float w = g_wt[e * TOKS + r];
            size_t yb = ((size_t)sl * TOKS + t) * HDIM + n0;
#pragma unroll
            for (int n = 0; n < 4; n++) {
                int col = wn * 32 + n * 8 + 2 * tig;
                float v0 = acc[m][n][half * 2 + 0], v1 = acc[m][n][half * 2 + 1];
                *reinterpret_cast<float2*>(g_y + yb + col) = make_float2(w * v0, w * v1);
            }
        }
    }
}

// ---------------- combine: out = y[slot0] + y[slot1] ----------------
__global__ void moe_combine(float* __restrict__ out) {
    size_t i = (size_t)blockIdx.x * 256 + threadIdx.x;
    const float4* y0 = reinterpret_cast<const float4*>(g_y);
    const float4* y1 = y0 + (size_t)TOKS * HDIM / 4;
    float4 a = y0[i], b = y1[i];
    reinterpret_cast<float4*>(out)[i] = make_float4(a.x + b.x, a.y + b.y, a.z + b.z, a.w + b.w);
}

// ---------------- launch ----------------
extern "C" void kernel_launch(void* const* d_in, const int* in_sizes, int n_in,
                              void* d_out, int out_size) {
    const float* x   = (const float*)d_in[0];
    const float* wg  = (const float*)d_in[1];
    const float* wgp = (const float*)d_in[2];
    const float* wup = (const float*)d_in[3];
    const float* wdp = (const float*)d_in[4];
    float* out = (float*)d_out;

    cudaFuncSetAttribute(moe_gateup, cudaFuncAttributeMaxDynamicSharedMemorySize, 110592);
    cudaFuncSetAttribute(moe_down,   cudaFuncAttributeMaxDynamicSharedMemorySize, 110592);

    conv_x<<<(TOKS * HDIM / 8) / 256, 256>>>(x);                          // #0 (+ zero g_cnt)
    conv_w3<<<dim3(64, 16, 24), 256>>>(wgp, wup, wdp);                    // #1 (all 3 weight sets)
    moe_router<<<TOKS / 8, 256>>>(x, wg, out + (size_t)TOKS * HDIM);      // #2
    moe_gateup<<<dim3(FDIM / 64, 32, NEXP), 256, 110592>>>();             // #3
    moe_down<<<dim3(HDIM / 128, 32, NEXP), 256, 110592>>>();              // #4
    moe_combine<<<(TOKS * HDIM / 4) / 256, 256>>>(out);                   // #5
}

// round 13
// speedup vs baseline: 1.1284x; 1.0240x over previous
#include <cuda_runtime.h>
#include <cuda_fp16.h>
#include <cstdint>

#define TOKS 8192
#define HDIM 1024
#define FDIM 4096
#define NEXP 8

// ---------------- scratch (__device__ globals; no allocation) ----------------
__device__ int    g_cnt[NEXP];
__device__ int    g_tok[NEXP * TOKS];
__device__ int    g_slot[NEXP * TOKS];
__device__ float  g_wt[NEXP * TOKS];
__device__ __half g_x16[(size_t)TOKS * HDIM];            // fp16 x (16 MB)
__device__ __half g_wg16[(size_t)NEXP * FDIM * HDIM];    // gate W, [e][n][k] (64 MB)
__device__ __half g_wu16[(size_t)NEXP * FDIM * HDIM];    // up   W, [e][n][k] (64 MB)
__device__ __half g_wd16[(size_t)NEXP * HDIM * FDIM];    // down W, [e][n][k] (64 MB)
__device__ __half g_h16[(size_t)2 * TOKS * FDIM];        // hidden (128 MB)
__device__ float  g_y[(size_t)2 * TOKS * HDIM];          // slot outputs (64 MB)

// ---------------- helpers ----------------
static __device__ __forceinline__ uint32_t smem_u32(const void* p) {
    uint32_t a;
    asm("{ .reg .u64 t; cvta.to.shared.u64 t, %1; cvt.u32.u64 %0, t; }" : "=r"(a) : "l"(p));
    return a;
}
static __device__ __forceinline__ void mma16(float* c, const uint32_t* a, const uint32_t* b) {
    asm volatile(
        "mma.sync.aligned.m16n8k16.row.col.f32.f16.f16.f32 "
        "{%0,%1,%2,%3}, {%4,%5,%6,%7}, {%8,%9}, {%0,%1,%2,%3};"
        : "+f"(c[0]), "+f"(c[1]), "+f"(c[2]), "+f"(c[3])
        : "r"(a[0]), "r"(a[1]), "r"(a[2]), "r"(a[3]), "r"(b[0]), "r"(b[1]));
}
#define LDSM4(r0, r1, r2, r3, addr)                                              \
    asm volatile("ldmatrix.sync.aligned.m8n8.x4.shared.b16 {%0,%1,%2,%3}, [%4];" \
                 : "=r"(r0), "=r"(r1), "=r"(r2), "=r"(r3) : "r"(addr))
#define CP16(dst, src, sz) \
    asm volatile("cp.async.cg.shared.global [%0], [%1], 16, %2;\n" ::"r"(dst), "l"(src), "r"(sz))
#define CP_COMMIT() asm volatile("cp.async.commit_group;\n" ::: "memory")
#define CP_WAITG1() asm volatile("cp.async.wait_group 1;\n" ::: "memory")
#define CP_WAIT0()  asm volatile("cp.async.wait_group 0;\n" ::: "memory")

static __device__ __forceinline__ float silu(float v) { return v / (1.f + __expf(-v)); }

static __device__ __forceinline__ int expert_off(int e) {
    int off = 0;
#pragma unroll
    for (int i = 0; i < NEXP; i++) if (i < e) off += g_cnt[i];
    return off;
}

// ---------------- convert x -> fp16 (also zeroes g_cnt) ----------------
__global__ void conv_x(const float* __restrict__ x) {
    if (blockIdx.x == 0 && threadIdx.x < NEXP) g_cnt[threadIdx.x] = 0;
    size_t i = ((size_t)blockIdx.x * 256 + threadIdx.x) * 8;
    float4 a = *reinterpret_cast<const float4*>(x + i);
    float4 b = *reinterpret_cast<const float4*>(x + i + 4);
    __half2 h[4];
    h[0] = __floats2half2_rn(a.x, a.y);
    h[1] = __floats2half2_rn(a.z, a.w);
    h[2] = __floats2half2_rn(b.x, b.y);
    h[3] = __floats2half2_rn(b.z, b.w);
    *reinterpret_cast<uint4*>(g_x16 + i) = *reinterpret_cast<uint4*>(h);
}

// ---------------- convert+transpose ALL W: [e][k][n] fp32 -> [e][n][k] fp16 ----------------
__global__ void conv_w3(const float* __restrict__ wgp, const float* __restrict__ wup,
                        const float* __restrict__ wdp) {
    __shared__ float t[64][65];
    int set = blockIdx.z >> 3, e = blockIdx.z & 7;
    const float* src; __half* dst; int Kd, Nd, k0, n0;
    if (set == 0)      { src = wgp; dst = g_wg16; Kd = HDIM; Nd = FDIM; }
    else if (set == 1) { src = wup; dst = g_wu16; Kd = HDIM; Nd = FDIM; }
    else               { src = wdp; dst = g_wd16; Kd = FDIM; Nd = HDIM; }
    if (set < 2) { k0 = blockIdx.y * 64; n0 = blockIdx.x * 64; }
    else         { k0 = blockIdx.x * 64; n0 = blockIdx.y * 64; }

    const float* S = src + ((size_t)e * Kd + k0) * Nd + n0;
    int tid = threadIdx.x;
    int kr = tid >> 4, nc = (tid & 15) * 4;
#pragma unroll
    for (int j = 0; j < 4; j++) {
        float4 v = *reinterpret_cast<const float4*>(S + (size_t)(kr + j * 16) * Nd + nc);
        t[kr + j * 16][nc + 0] = v.x;
        t[kr + j * 16][nc + 1] = v.y;
        t[kr + j * 16][nc + 2] = v.z;
        t[kr + j * 16][nc + 3] = v.w;
    }
    __syncthreads();
    int nr = tid >> 2, kc = (tid & 3) * 16;
    __half hb[16];
#pragma unroll
    for (int q = 0; q < 16; q++) hb[q] = __float2half_rn(t[kc + q][nr]);
    __half* D = dst + ((size_t)e * Nd + n0 + nr) * Kd + k0 + kc;
    *reinterpret_cast<uint4*>(D)     = *reinterpret_cast<uint4*>(hb);
    *reinterpret_cast<uint4*>(D + 8) = *reinterpret_cast<uint4*>(hb + 8);
}

// ---------------- router ----------------
__global__ void moe_router(const float* __restrict__ x, const float* __restrict__ wg,
                           float* __restrict__ logits_out) {
    int t = blockIdx.x * 8 + (threadIdx.x >> 5);
    int lane = threadIdx.x & 31;
    const float* xr = x + (size_t)t * HDIM;
    float acc[8] = {0.f, 0.f, 0.f, 0.f, 0.f, 0.f, 0.f, 0.f};
    for (int j = lane; j < HDIM; j += 32) {
        float xv = xr[j];
        const float4* w4 = reinterpret_cast<const float4*>(wg + (size_t)j * NEXP);
        float4 a = w4[0], b = w4[1];
        acc[0] += xv * a.x; acc[1] += xv * a.y; acc[2] += xv * a.z; acc[3] += xv * a.w;
        acc[4] += xv * b.x; acc[5] += xv * b.y; acc[6] += xv * b.z; acc[7] += xv * b.w;
    }
#pragma unroll
    for (int o = 16; o > 0; o >>= 1)
#pragma unroll
        for (int k = 0; k < 8; k++) acc[k] += __shfl_xor_sync(0xffffffffu, acc[k], o);

    if (lane == 0) {
#pragma unroll
        for (int k = 0; k < 8; k++) logits_out[(size_t)t * NEXP + k] = acc[k];
        int i0 = 0; float v0 = acc[0];
#pragma unroll
        for (int k = 1; k < 8; k++) if (acc[k] > v0) { v0 = acc[k]; i0 = k; }
        int i1 = -1; float v1 = -3.4e38f;
#pragma unroll
        for (int k = 0; k < 8; k++) if (k != i0 && acc[k] > v1) { v1 = acc[k]; i1 = k; }
        float w0 = 1.f / (1.f + __expf(v1 - v0));
        float w1 = 1.f - w0;
        int p0 = atomicAdd(&g_cnt[i0], 1);
        g_tok[i0 * TOKS + p0] = t; g_slot[i0 * TOKS + p0] = 0; g_wt[i0 * TOKS + p0] = w0;
        int p1 = atomicAdd(&g_cnt[i1], 1);
        g_tok[i1 * TOKS + p1] = t; g_slot[i1 * TOKS + p1] = 1; g_wt[i1 * TOKS + p1] = w1;
    }
}

// ---------------- fused gate+up GEMM (fp16, ldmatrix, BK=64, 3-stage) ----------------
// BM=128, BN=64 per side, BK=64, pitch 72 halves. Stage 36864B, 3 stages, 2 CTAs/SM.
// Inner k-step: LDSM/MMA issue interleaved so tensor work starts while frags load.
__global__ void __launch_bounds__(256, 2)
moe_gateup() {
    int e = blockIdx.z;
    int cnt = g_cnt[e];
    int base = blockIdx.y * 128;
    if (base >= cnt) return;
    int n0 = blockIdx.x * 64;
    int off = expert_off(e);
    const __half* wge = g_wg16 + (size_t)e * FDIM * HDIM;
    const __half* wue = g_wu16 + (size_t)e * FDIM * HDIM;

    extern __shared__ char smem8[];
    uint32_t su = smem_u32(smem8);
    const uint32_t STG = 36864;

    int tid = threadIdx.x, lane = tid & 31;
    int gid = lane >> 2, tig = lane & 3;
    int wid = tid >> 5, wm = wid >> 2, wn = wid & 3;

    const __half* asrc[4]; uint32_t asz[4], adst[4];
#pragma unroll
    for (int j = 0; j < 4; j++) {
        int idx = tid + j * 256;
        int row = idx >> 3, c = idx & 7;
        int r = base + row;
        bool v = r < cnt;
        int tok = v ? g_tok[e * TOKS + r] : 0;
        asrc[j] = g_x16 + (size_t)tok * HDIM + c * 8;
        asz[j] = v ? 16u : 0u;
        adst[j] = (uint32_t)(row * 144 + c * 16);
    }
    const __half* gsrc[2]; const __half* usrc[2]; uint32_t bdst[2];
#pragma unroll
    for (int j = 0; j < 2; j++) {
        int idx = tid + j * 256;
        int n = idx >> 3, c = idx & 7;
        gsrc[j] = wge + (size_t)(n0 + n) * HDIM + c * 8;
        usrc[j] = wue + (size_t)(n0 + n) * HDIM + c * 8;
        bdst[j] = (uint32_t)(n * 144 + c * 16);
    }

    uint32_t aoff[4];
#pragma unroll
    for (int m = 0; m < 4; m++)
        aoff[m] = (uint32_t)(((wm * 64 + m * 16 + (lane & 15)) * 72 + (lane >> 4) * 8) * 2);
    uint32_t boff = (uint32_t)(((wn * 16 + (lane & 7) + ((lane >> 4) & 1) * 8) * 72 +
                                ((lane >> 3) & 1) * 8) * 2);

    float accG[4][2][4], accU[4][2][4];
#pragma unroll
    for (int m = 0; m < 4; m++)
#pragma unroll
        for (int n = 0; n < 2; n++)
#pragma unroll
            for (int q = 0; q < 4; q++) { accG[m][n][q] = 0.f; accU[m][n][q] = 0.f; }

    const int KI = HDIM / 64;  // 16

#define GU_ISSUE(s, k0)                                                  \
    do {                                                                 \
        uint32_t ab = su + (uint32_t)(s) * STG;                          \
        _Pragma("unroll") for (int j = 0; j < 4; j++)                    \
            CP16(ab + adst[j], asrc[j] + (k0), asz[j]);                  \
        _Pragma("unroll") for (int j = 0; j < 2; j++)                    \
            CP16(ab + 18432u + bdst[j], gsrc[j] + (k0), 16u);            \
        _Pragma("unroll") for (int j = 0; j < 2; j++)                    \
            CP16(ab + 27648u + bdst[j], usrc[j] + (k0), 16u);            \
        CP_COMMIT();                                                     \
    } while (0)

    GU_ISSUE(0, 0);
    GU_ISSUE(1, 64);

    int sC = 0, sP = 2;
    for (int i = 0; i < KI; i++) {
        if (i + 1 < KI) CP_WAITG1(); else CP_WAIT0();
        __syncthreads();
        if (i + 2 < KI) {
            GU_ISSUE(sP, (i + 2) * 64);
            sP = (sP == 2) ? 0 : sP + 1;
        }
        uint32_t ab = su + (uint32_t)sC * STG;
        sC = (sC == 2) ? 0 : sC + 1;
#pragma unroll
        for (int kk = 0; kk < 4; kk++) {
            uint32_t kb = (uint32_t)(kk * 32);  // 16 halves per k-step
            uint32_t af[4][4], bg[4], bu[4];
            // interleaved issue: frags for m-step j+1 load while m-step j computes
            LDSM4(bg[0], bg[1], bg[2], bg[3], ab + 18432u + boff + kb);
            LDSM4(af[0][0], af[0][1], af[0][2], af[0][3], ab + aoff[0] + kb);
            LDSM4(bu[0], bu[1], bu[2], bu[3], ab + 27648u + boff + kb);
            LDSM4(af[1][0], af[1][1], af[1][2], af[1][3], ab + aoff[1] + kb);
            mma16(accG[0][0], af[0], bg + 0);
            mma16(accG[0][1], af[0], bg + 2);
            mma16(accU[0][0], af[0], bu + 0);
            mma16(accU[0][1], af[0], bu + 2);
            LDSM4(af[2][0], af[2][1], af[2][2], af[2][3], ab + aoff[2] + kb);
            mma16(accG[1][0], af[1], bg + 0);
            mma16(accG[1][1], af[1], bg + 2);
            mma16(accU[1][0], af[1], bu + 0);
            mma16(accU[1][1], af[1], bu + 2);
            LDSM4(af[3][0], af[3][1], af[3][2], af[3][3], ab + aoff[3] + kb);
            mma16(accG[2][0], af[2], bg + 0);
            mma16(accG[2][1], af[2], bg + 2);
            mma16(accU[2][0], af[2], bu + 0);
            mma16(accU[2][1], af[2], bu + 2);
            mma16(accG[3][0], af[3], bg + 0);
            mma16(accG[3][1], af[3], bg + 2);
            mma16(accU[3][0], af[3], bu + 0);
            mma16(accU[3][1], af[3], bu + 2);
        }
    }
#undef GU_ISSUE

    // epilogue: g_h16 = fp16(silu(g) * u)
#pragma unroll
    for (int m = 0; m < 4; m++) {
#pragma unroll
        for (int half = 0; half < 2; half++) {
            int R = wm * 64 + m * 16 + gid + half * 8;
            int r = base + R;
            if (r >= cnt) continue;
            size_t rb = (size_t)(off + r) * FDIM + n0;
#pragma unroll
            for (int n = 0; n < 2; n++) {
                int col = wn * 16 + n * 8 + 2 * tig;
                float h0 = silu(accG[m][n][half * 2 + 0]) * accU[m][n][half * 2 + 0];
                float h1 = silu(accG[m][n][half * 2 + 1]) * accU[m][n][half * 2 + 1];
                *reinterpret_cast<__half2*>(g_h16 + rb + col) = __floats2half2_rn(h0, h1);
            }
        }
    }
}

// ---------------- down GEMM: y[slot][tok] = w * (g_h16 @ Wd), BK=64, 3-stage ----------------
__global__ void __launch_bounds__(256, 2)
moe_down() {
    int e = blockIdx.z;
    int cnt = g_cnt[e];
    int base = blockIdx.y * 128;
    if (base >= cnt) return;
    int n0 = blockIdx.x * 128;
    int off = expert_off(e);
    const __half* wde = g_wd16 + (size_t)e * HDIM * FDIM;

    extern __shared__ char smem8[];
    uint32_t su = smem_u32(smem8);
    const uint32_t STG = 36864;

    int tid = threadIdx.x, lane = tid & 31;
    int gid = lane >> 2, tig = lane & 3;
    int wid = tid >> 5, wm = wid >> 2, wn = wid & 3;

    const __half* asrc[4]; uint32_t asz[4], adst[4];
#pragma unroll
    for (int j = 0; j < 4; j++) {
        int idx = tid + j * 256;
        int row = idx >> 3, c = idx & 7;
        int r = base + row;
        bool v = r < cnt;
        size_t arow = v ? (size_t)(off + r) : 0;
        asrc[j] = g_h16 + arow * FDIM + c * 8;
        asz[j] = v ? 16u : 0u;
        adst[j] = (uint32_t)(row * 144 + c * 16);
    }
    const __half* bsrc[4]; uint32_t bdst[4];
#pragma unroll
    for (int j = 0; j < 4; j++) {
        int idx = tid + j * 256;
        int n = idx >> 3, c = idx & 7;
        bsrc[j] = wde + (size_t)(n0 + n) * FDIM + c * 8;
        bdst[j] = (uint32_t)(n * 144 + c * 16);
    }

    uint32_t aoff[4];
#pragma unroll
    for (int m = 0; m < 4; m++)
        aoff[m] = (uint32_t)(((wm * 64 + m * 16 + (lane & 15)) * 72 + (lane >> 4) * 8) * 2);
    uint32_t boff[2];
#pragma unroll
    for (int p = 0; p < 2; p++)
        boff[p] = (uint32_t)(((wn * 32 + p * 16 + (lane & 7) + ((lane >> 4) & 1) * 8) * 72 +
                              ((lane >> 3) & 1) * 8) * 2);

    float acc[4][4][4];
#pragma unroll
    for (int m = 0; m < 4; m++)
#pragma unroll
        for (int n = 0; n < 4; n++)
#pragma unroll
            for (int q = 0; q < 4; q++) acc[m][n][q] = 0.f;

    const int KI = FDIM / 64;  // 64

#define DN_ISSUE(s, k0)                                                  \
    do {                                                                 \
        uint32_t ab = su + (uint32_t)(s) * STG;                          \
        _Pragma("unroll") for (int j = 0; j < 4; j++)                    \
            CP16(ab + adst[j], asrc[j] + (k0), asz[j]);                  \
        _Pragma("unroll") for (int j = 0; j < 4; j++)                    \
            CP16(ab + 18432u + bdst[j], bsrc[j] + (k0), 16u);            \
        CP_COMMIT();                                                     \
    } while (0)

    DN_ISSUE(0, 0);
    DN_ISSUE(1, 64);

    int sC = 0, sP = 2;
    for (int i = 0; i < KI; i++) {
        if (i + 1 < KI) CP_WAITG1(); else CP_WAIT0();
        __syncthreads();
        if (i + 2 < KI) {
            DN_ISSUE(sP, (i + 2) * 64);
            sP = (sP == 2) ? 0 : sP + 1;
        }
        uint32_t ab = su + (uint32_t)sC * STG;
        sC = (sC == 2) ? 0 : sC + 1;
#pragma unroll
        for (int kk = 0; kk < 4; kk++) {
            uint32_t kb = (uint32_t)(kk * 32);
            uint32_t af[4][4], bf[2][4];
            // interleaved issue
            LDSM4(bf[0][0], bf[0][1], bf[0][2], bf[0][3], ab + 18432u + boff[0] + kb);
            LDSM4(af[0][0], af[0][1], af[0][2], af[0][3], ab + aoff[0] + kb);
            LDSM4(bf[1][0], bf[1][1], bf[1][2], bf[1][3], ab + 18432u + boff[1] + kb);
            LDSM4(af[1][0], af[1][1], af[1][2], af[1][3], ab + aoff[1] + kb);
            mma16(acc[0][0], af[0], bf[0] + 0);
            mma16(acc[0][1], af[0], bf[0] + 2);
            mma16(acc[0][2], af[0], bf[1] + 0);
            mma16(acc[0][3], af[0], bf[1] + 2);
            LDSM4(af[2][0], af[2][1], af[2][2], af[2][3], ab + aoff[2] + kb);
            mma16(acc[1][0], af[1], bf[0] + 0);
            mma16(acc[1][1], af[1], bf[0] + 2);
            mma16(acc[1][2], af[1], bf[1] + 0);
            mma16(acc[1][3], af[1], bf[1] + 2);
            LDSM4(af[3][0], af[3][1], af[3][2], af[3][3], ab + aoff[3] + kb);
            mma16(acc[2][0], af[2], bf[0] + 0);
            mma16(acc[2][1], af[2], bf[0] + 2);
            mma16(acc[2][2], af[2], bf[1] + 0);
            mma16(acc[2][3], af[2], bf[1] + 2);
            mma16(acc[3][0], af[3], bf[0] + 0);
            mma16(acc[3][1], af[3], bf[0] + 2);
            mma16(acc[3][2], af[3], bf[1] + 0);
            mma16(acc[3][3], af[3], bf[1] + 2);
        }
    }
#undef DN_ISSUE

    // epilogue: weighted scatter
#pragma unroll
    for (int m = 0; m < 4; m++) {
#pragma unroll
        for (int half = 0; half < 2; half++) {
            int R = wm * 64 + m * 16 + gid + half * 8;
            int r = base + R;
            if (r >= cnt) continue;
            int t = g_tok[e * TOKS + r];
            int sl = g_slot[e * TOKS + r];
            float w = g_wt[e * TOKS + r];
            size_t yb = ((size_t)sl * TOKS + t) * HDIM + n0;
#pragma unroll
            for (int n = 0; n < 4; n++) {
                int col = wn * 32 + n * 8 + 2 * tig;
                float v0 = acc[m][n][half * 2 + 0], v1 = acc[m][n][half * 2 + 1];
                *reinterpret_cast<float2*>(g_y + yb + col) = make_float2(w * v0, w * v1);
            }
        }
    }
}

// ---------------- combine: out = y[slot0] + y[slot1] ----------------
__global__ void moe_combine(float* __restrict__ out) {
    size_t i = (size_t)blockIdx.x * 256 + threadIdx.x;
    const float4* y0 = reinterpret_cast<const float4*>(g_y);
    const float4* y1 = y0 + (size_t)TOKS * HDIM / 4;
    float4 a = y0[i], b = y1[i];
    reinterpret_cast<float4*>(out)[i] = make_float4(a.x + b.x, a.y + b.y, a.z + b.z, a.w + b.w);
}

// ---------------- launch ----------------
extern "C" void kernel_launch(void* const* d_in, const int* in_sizes, int n_in,
                              void* d_out, int out_size) {
    const float* x   = (const float*)d_in[0];
    const float* wg  = (const float*)d_in[1];
    const float* wgp = (const float*)d_in[2];
    const float* wup = (const float*)d_in[3];
    const float* wdp = (const float*)d_in[4];
    float* out = (float*)d_out;

    cudaFuncSetAttribute(moe_gateup, cudaFuncAttributeMaxDynamicSharedMemorySize, 110592);
    cudaFuncSetAttribute(moe_down,   cudaFuncAttributeMaxDynamicSharedMemorySize, 110592);

    conv_x<<<(TOKS * HDIM / 8) / 256, 256>>>(x);                          // #0 (+ zero g_cnt)
    conv_w3<<<dim3(64, 16, 24), 256>>>(wgp, wup, wdp);                    // #1 (all 3 weight sets)
    moe_router<<<TOKS / 8, 256>>>(x, wg, out + (size_t)TOKS * HDIM);      // #2
    moe_gateup<<<dim3(FDIM / 64, 32, NEXP), 256, 110592>>>();             // #3
    moe_down<<<dim3(HDIM / 128, 32, NEXP), 256, 110592>>>();              // #4
    moe_combine<<<(TOKS * HDIM / 4) / 256, 256>>>(out);                   // #5
}

// round 14
// speedup vs baseline: 1.1947x; 1.0588x over previous
#include <cuda_runtime.h>
#include <cuda_fp16.h>
#include <cstdint>

#define TOKS 8192
#define HDIM 1024
#define FDIM 4096
#define NEXP 8

// ---------------- scratch (__device__ globals; no allocation) ----------------
__device__ int    g_cnt[NEXP];
__device__ int    g_tok[NEXP * TOKS];
__device__ int    g_slot[NEXP * TOKS];
__device__ float  g_wt[NEXP * TOKS];
__device__ __half g_x16[(size_t)TOKS * HDIM];            // fp16 x (16 MB)
__device__ __half g_wg16[(size_t)NEXP * FDIM * HDIM];    // gate W, [e][n][k] (64 MB)
__device__ __half g_wu16[(size_t)NEXP * FDIM * HDIM];    // up   W, [e][n][k] (64 MB)
__device__ __half g_wd16[(size_t)NEXP * HDIM * FDIM];    // down W, [e][n][k] (64 MB)
__device__ __half g_h16[(size_t)2 * TOKS * FDIM];        // hidden (128 MB)
__device__ float  g_y[(size_t)4 * TOKS * HDIM];          // [split][slot] outputs (128 MB)

// ---------------- helpers ----------------
static __device__ __forceinline__ uint32_t smem_u32(const void* p) {
    uint32_t a;
    asm("{ .reg .u64 t; cvta.to.shared.u64 t, %1; cvt.u32.u64 %0, t; }" : "=r"(a) : "l"(p));
    return a;
}
static __device__ __forceinline__ void mma16(float* c, const uint32_t* a, const uint32_t* b) {
    asm volatile(
        "mma.sync.aligned.m16n8k16.row.col.f32.f16.f16.f32 "
        "{%0,%1,%2,%3}, {%4,%5,%6,%7}, {%8,%9}, {%0,%1,%2,%3};"
        : "+f"(c[0]), "+f"(c[1]), "+f"(c[2]), "+f"(c[3])
        : "r"(a[0]), "r"(a[1]), "r"(a[2]), "r"(a[3]), "r"(b[0]), "r"(b[1]));
}
#define LDSM4(r0, r1, r2, r3, addr)                                              \
    asm volatile("ldmatrix.sync.aligned.m8n8.x4.shared.b16 {%0,%1,%2,%3}, [%4];" \
                 : "=r"(r0), "=r"(r1), "=r"(r2), "=r"(r3) : "r"(addr))
#define CP16(dst, src, sz) \
    asm volatile("cp.async.cg.shared.global [%0], [%1], 16, %2;\n" ::"r"(dst), "l"(src), "r"(sz))
#define CP_COMMIT() asm volatile("cp.async.commit_group;\n" ::: "memory")
#define CP_WAITG1() asm volatile("cp.async.wait_group 1;\n" ::: "memory")
#define CP_WAIT0()  asm volatile("cp.async.wait_group 0;\n" ::: "memory")

static __device__ __forceinline__ float silu(float v) { return v / (1.f + __expf(-v)); }

static __device__ __forceinline__ int expert_off(int e) {
    int off = 0;
#pragma unroll
    for (int i = 0; i < NEXP; i++) if (i < e) off += g_cnt[i];
    return off;
}

// ---------------- convert x -> fp16 (also zeroes g_cnt) ----------------
__global__ void conv_x(const float* __restrict__ x) {
    if (blockIdx.x == 0 && threadIdx.x < NEXP) g_cnt[threadIdx.x] = 0;
    size_t i = ((size_t)blockIdx.x * 256 + threadIdx.x) * 8;
    float4 a = *reinterpret_cast<const float4*>(x + i);
    float4 b = *reinterpret_cast<const float4*>(x + i + 4);
    __half2 h[4];
    h[0] = __floats2half2_rn(a.x, a.y);
    h[1] = __floats2half2_rn(a.z, a.w);
    h[2] = __floats2half2_rn(b.x, b.y);
    h[3] = __floats2half2_rn(b.z, b.w);
    *reinterpret_cast<uint4*>(g_x16 + i) = *reinterpret_cast<uint4*>(h);
}

// ---------------- convert+transpose ALL W: [e][k][n] fp32 -> [e][n][k] fp16 ----------------
__global__ void conv_w3(const float* __restrict__ wgp, const float* __restrict__ wup,
                        const float* __restrict__ wdp) {
    __shared__ float t[64][65];
    int set = blockIdx.z >> 3, e = blockIdx.z & 7;
    const float* src; __half* dst; int Kd, Nd, k0, n0;
    if (set == 0)      { src = wgp; dst = g_wg16; Kd = HDIM; Nd = FDIM; }
    else if (set == 1) { src = wup; dst = g_wu16; Kd = HDIM; Nd = FDIM; }
    else               { src = wdp; dst = g_wd16; Kd = FDIM; Nd = HDIM; }
    if (set < 2) { k0 = blockIdx.y * 64; n0 = blockIdx.x * 64; }
    else         { k0 = blockIdx.x * 64; n0 = blockIdx.y * 64; }

    const float* S = src + ((size_t)e * Kd + k0) * Nd + n0;
    int tid = threadIdx.x;
    int kr = tid >> 4, nc = (tid & 15) * 4;
#pragma unroll
    for (int j = 0; j < 4; j++) {
        float4 v = *reinterpret_cast<const float4*>(S + (size_t)(kr + j * 16) * Nd + nc);
        t[kr + j * 16][nc + 0] = v.x;
        t[kr + j * 16][nc + 1] = v.y;
        t[kr + j * 16][nc + 2] = v.z;
        t[kr + j * 16][nc + 3] = v.w;
    }
    __syncthreads();
    int nr = tid >> 2, kc = (tid & 3) * 16;
    __half hb[16];
#pragma unroll
    for (int q = 0; q < 16; q++) hb[q] = __float2half_rn(t[kc + q][nr]);
    __half* D = dst + ((size_t)e * Nd + n0 + nr) * Kd + k0 + kc;
    *reinterpret_cast<uint4*>(D)     = *reinterpret_cast<uint4*>(hb);
    *reinterpret_cast<uint4*>(D + 8) = *reinterpret_cast<uint4*>(hb + 8);
}

// ---------------- router ----------------
__global__ void moe_router(const float* __restrict__ x, const float* __restrict__ wg,
                           float* __restrict__ logits_out) {
    int t = blockIdx.x * 8 + (threadIdx.x >> 5);
    int lane = threadIdx.x & 31;
    const float* xr = x + (size_t)t * HDIM;
    float acc[8] = {0.f, 0.f, 0.f, 0.f, 0.f, 0.f, 0.f, 0.f};
    for (int j = lane; j < HDIM; j += 32) {
        float xv = xr[j];
        const float4* w4 = reinterpret_cast<const float4*>(wg + (size_t)j * NEXP);
        float4 a = w4[0], b = w4[1];
        acc[0] += xv * a.x; acc[1] += xv * a.y; acc[2] += xv * a.z; acc[3] += xv * a.w;
        acc[4] += xv * b.x; acc[5] += xv * b.y; acc[6] += xv * b.z; acc[7] += xv * b.w;
    }
#pragma unroll
    for (int o = 16; o > 0; o >>= 1)
#pragma unroll
        for (int k = 0; k < 8; k++) acc[k] += __shfl_xor_sync(0xffffffffu, acc[k], o);

    if (lane == 0) {
#pragma unroll
        for (int k = 0; k < 8; k++) logits_out[(size_t)t * NEXP + k] = acc[k];
        int i0 = 0; float v0 = acc[0];
#pragma unroll
        for (int k = 1; k < 8; k++) if (acc[k] > v0) { v0 = acc[k]; i0 = k; }
        int i1 = -1; float v1 = -3.4e38f;
#pragma unroll
        for (int k = 0; k < 8; k++) if (k != i0 && acc[k] > v1) { v1 = acc[k]; i1 = k; }
        float w0 = 1.f / (1.f + __expf(v1 - v0));
        float w1 = 1.f - w0;
        int p0 = atomicAdd(&g_cnt[i0], 1);
        g_tok[i0 * TOKS + p0] = t; g_slot[i0 * TOKS + p0] = 0; g_wt[i0 * TOKS + p0] = w0;
        int p1 = atomicAdd(&g_cnt[i1], 1);
        g_tok[i1 * TOKS + p1] = t; g_slot[i1 * TOKS + p1] = 1; g_wt[i1 * TOKS + p1] = w1;
    }
}

// ---------------- fused gate+up GEMM (fp16, ldmatrix, BK=64, 3-stage) ----------------
// BM=128, BN=64 per side, BK=64, pitch 72 halves. Stage 36864B, 3 stages, 2 CTAs/SM.
// cp.async issue moved after the first k-step so first MMAs start immediately.
__global__ void __launch_bounds__(256, 2)
moe_gateup() {
    int e = blockIdx.z;
    int cnt = g_cnt[e];
    int base = blockIdx.y * 128;
    if (base >= cnt) return;
    int n0 = blockIdx.x * 64;
    int off = expert_off(e);
    const __half* wge = g_wg16 + (size_t)e * FDIM * HDIM;
    const __half* wue = g_wu16 + (size_t)e * FDIM * HDIM;

    extern __shared__ char smem8[];
    uint32_t su = smem_u32(smem8);
    const uint32_t STG = 36864;

    int tid = threadIdx.x, lane = tid & 31;
    int gid = lane >> 2, tig = lane & 3;
    int wid = tid >> 5, wm = wid >> 2, wn = wid & 3;

    const __half* asrc[4]; uint32_t asz[4], adst[4];
#pragma unroll
    for (int j = 0; j < 4; j++) {
        int idx = tid + j * 256;
        int row = idx >> 3, c = idx & 7;
        int r = base + row;
        bool v = r < cnt;
        int tok = v ? g_tok[e * TOKS + r] : 0;
        asrc[j] = g_x16 + (size_t)tok * HDIM + c * 8;
        asz[j] = v ? 16u : 0u;
        adst[j] = (uint32_t)(row * 144 + c * 16);
    }
    const __half* gsrc[2]; const __half* usrc[2]; uint32_t bdst[2];
#pragma unroll
    for (int j = 0; j < 2; j++) {
        int idx = tid + j * 256;
        int n = idx >> 3, c = idx & 7;
        gsrc[j] = wge + (size_t)(n0 + n) * HDIM + c * 8;
        usrc[j] = wue + (size_t)(n0 + n) * HDIM + c * 8;
        bdst[j] = (uint32_t)(n * 144 + c * 16);
    }

    uint32_t aoff[4];
#pragma unroll
    for (int m = 0; m < 4; m++)
        aoff[m] = (uint32_t)(((wm * 64 + m * 16 + (lane & 15)) * 72 + (lane >> 4) * 8) * 2);
    uint32_t boff = (uint32_t)(((wn * 16 + (lane & 7) + ((lane >> 4) & 1) * 8) * 72 +
                                ((lane >> 3) & 1) * 8) * 2);

    float accG[4][2][4], accU[4][2][4];
#pragma unroll
    for (int m = 0; m < 4; m++)
#pragma unroll
        for (int n = 0; n < 2; n++)
#pragma unroll
            for (int q = 0; q < 4; q++) { accG[m][n][q] = 0.f; accU[m][n][q] = 0.f; }

    const int KI = HDIM / 64;  // 16

#define GU_ISSUE(s, k0)                                                  \
    do {                                                                 \
        uint32_t abw = su + (uint32_t)(s) * STG;                         \
        _Pragma("unroll") for (int j = 0; j < 4; j++)                    \
            CP16(abw + adst[j], asrc[j] + (k0), asz[j]);                 \
        _Pragma("unroll") for (int j = 0; j < 2; j++)                    \
            CP16(abw + 18432u + bdst[j], gsrc[j] + (k0), 16u);           \
        _Pragma("unroll") for (int j = 0; j < 2; j++)                    \
            CP16(abw + 27648u + bdst[j], usrc[j] + (k0), 16u);           \
        CP_COMMIT();                                                     \
    } while (0)

#define GU_STEP(kb)                                                      \
    do {                                                                 \
        uint32_t af[4][4], bg[4], bu[4];                                 \
        LDSM4(bg[0], bg[1], bg[2], bg[3], ab + 18432u + boff + (kb));    \
        LDSM4(af[0][0], af[0][1], af[0][2], af[0][3], ab + aoff[0] + (kb)); \
        LDSM4(bu[0], bu[1], bu[2], bu[3], ab + 27648u + boff + (kb));    \
        LDSM4(af[1][0], af[1][1], af[1][2], af[1][3], ab + aoff[1] + (kb)); \
        mma16(accG[0][0], af[0], bg + 0);                                \
        mma16(accG[0][1], af[0], bg + 2);                                \
        mma16(accU[0][0], af[0], bu + 0);                                \
        mma16(accU[0][1], af[0], bu + 2);                                \
        LDSM4(af[2][0], af[2][1], af[2][2], af[2][3], ab + aoff[2] + (kb)); \
        mma16(accG[1][0], af[1], bg + 0);                                \
        mma16(accG[1][1], af[1], bg + 2);                                \
        mma16(accU[1][0], af[1], bu + 0);                                \
        mma16(accU[1][1], af[1], bu + 2);                                \
        LDSM4(af[3][0], af[3][1], af[3][2], af[3][3], ab + aoff[3] + (kb)); \
        mma16(accG[2][0], af[2], bg + 0);                                \
        mma16(accG[2][1], af[2], bg + 2);                                \
        mma16(accU[2][0], af[2], bu + 0);                                \
        mma16(accU[2][1], af[2], bu + 2);                                \
        mma16(accG[3][0], af[3], bg + 0);                                \
        mma16(accG[3][1], af[3], bg + 2);                                \
        mma16(accU[3][0], af[3], bu + 0);                                \
        mma16(accU[3][1], af[3], bu + 2);                                \
    } while (0)

    GU_ISSUE(0, 0);
    GU_ISSUE(1, 64);

    int sC = 0, sP = 2;
    for (int i = 0; i < KI; i++) {
        if (i + 1 < KI) CP_WAITG1(); else CP_WAIT0();
        __syncthreads();
        uint32_t ab = su + (uint32_t)sC * STG;
        sC = (sC == 2) ? 0 : sC + 1;
        GU_STEP(0);
        if (i + 2 < KI) {
            GU_ISSUE(sP, (i + 2) * 64);
            sP = (sP == 2) ? 0 : sP + 1;
        }
        GU_STEP(32);
        GU_STEP(64);
        GU_STEP(96);
    }
#undef GU_ISSUE
#undef GU_STEP

    // epilogue: g_h16 = fp16(silu(g) * u)
#pragma unroll
    for (int m = 0; m < 4; m++) {
#pragma unroll
        for (int half = 0; half < 2; half++) {
            int R = wm * 64 + m * 16 + gid + half * 8;
            int r = base + R;
            if (r >= cnt) continue;
            size_t rb = (size_t)(off + r) * FDIM + n0;
#pragma unroll
            for (int n = 0; n < 2; n++) {
                int col = wn * 16 + n * 8 + 2 * tig;
                float h0 = silu(accG[m][n][half * 2 + 0]) * accU[m][n][half * 2 + 0];
                float h1 = silu(accG[m][n][half * 2 + 1]) * accU[m][n][half * 2 + 1];
                *reinterpret_cast<__half2*>(g_h16 + rb + col) = __floats2half2_rn(h0, h1);
            }
        }
    }
}

// ---------------- down GEMM, split-K=2: y[split][slot][tok] = w * (g_h16 @ Wd) ----------------
// blockIdx.z: e = z&7, split = z>>3. Each CTA covers 32 of 64 k-tiles.
__global__ void __launch_bounds__(256, 2)
moe_down() {
    int e = blockIdx.z & 7;
    int split = blockIdx.z >> 3;
    int cnt = g_cnt[e];
    int base = blockIdx.y * 128;
    if (base >= cnt) return;
    int n0 = blockIdx.x * 128;
    int off = expert_off(e);
    int kbase = split * (FDIM / 2);  // element offset
    const __half* wde = g_wd16 + (size_t)e * HDIM * FDIM;

    extern __shared__ char smem8[];
    uint32_t su = smem_u32(smem8);
    const uint32_t STG = 36864;

    int tid = threadIdx.x, lane = tid & 31;
    int gid = lane >> 2, tig = lane & 3;
    int wid = tid >> 5, wm = wid >> 2, wn = wid & 3;

    const __half* asrc[4]; uint32_t asz[4], adst[4];
#pragma unroll
    for (int j = 0; j < 4; j++) {
        int idx = tid + j * 256;
        int row = idx >> 3, c = idx & 7;
        int r = base + row;
        bool v = r < cnt;
        size_t arow = v ? (size_t)(off + r) : 0;
        asrc[j] = g_h16 + arow * FDIM + kbase + c * 8;
        asz[j] = v ? 16u : 0u;
        adst[j] = (uint32_t)(row * 144 + c * 16);
    }
    const __half* bsrc[4]; uint32_t bdst[4];
#pragma unroll
    for (int j = 0; j < 4; j++) {
        int idx = tid + j * 256;
        int n = idx >> 3, c = idx & 7;
        bsrc[j] = wde + (size_t)(n0 + n) * FDIM + kbase + c * 8;
        bdst[j] = (uint32_t)(n * 144 + c * 16);
    }

    uint32_t aoff[4];
#pragma unroll
    for (int m = 0; m < 4; m++)
        aoff[m] = (uint32_t)(((wm * 64 + m * 16 + (lane & 15)) * 72 + (lane >> 4) * 8) * 2);
    uint32_t boff[2];
#pragma unroll
    for (int p = 0; p < 2; p++)
        boff[p] = (uint32_t)(((wn * 32 + p * 16 + (lane & 7) + ((lane >> 4) & 1) * 8) * 72 +
                              ((lane >> 3) & 1) * 8) * 2);

    float acc[4][4][4];
#pragma unroll
    for (int m = 0; m < 4; m++)
#pragma unroll
        for (int n = 0; n < 4; n++)
#pragma unroll
            for (int q = 0; q < 4; q++) acc[m][n][q] = 0.f;

    const int KI = FDIM / 128;  // 32 tiles per split

#define DN_ISSUE(s, k0)                                                  \
    do {                                                                 \
        uint32_t abw = su + (uint32_t)(s) * STG;                         \
        _Pragma("unroll") for (int j = 0; j < 4; j++)                    \
            CP16(abw + adst[j], asrc[j] + (k0), asz[j]);                 \
        _Pragma("unroll") for (int j = 0; j < 4; j++)                    \
            CP16(abw + 18432u + bdst[j], bsrc[j] + (k0), 16u);           \
        CP_COMMIT();                                                     \
    } while (0)

#define DN_STEP(kb)                                                      \
    do {                                                                 \
        uint32_t af[4][4], bf[2][4];                                     \
        LDSM4(bf[0][0], bf[0][1], bf[0][2], bf[0][3], ab + 18432u + boff[0] + (kb)); \
        LDSM4(af[0][0], af[0][1], af[0][2], af[0][3], ab + aoff[0] + (kb)); \
        LDSM4(bf[1][0], bf[1][1], bf[1][2], bf[1][3], ab + 18432u + boff[1] + (kb)); \
        LDSM4(af[1][0], af[1][1], af[1][2], af[1][3], ab + aoff[1] + (kb)); \
        mma16(acc[0][0], af[0], bf[0] + 0);                              \
        mma16(acc[0][1], af[0], bf[0] + 2);                              \
        mma16(acc[0][2], af[0], bf[1] + 0);                              \
        mma16(acc[0][3], af[0], bf[1] + 2);                              \
        LDSM4(af[2][0], af[2][1], af[2][2], af[2][3], ab + aoff[2] + (kb)); \
        mma16(acc[1][0], af[1], bf[0] + 0);                              \
        mma16(acc[1][1], af[1], bf[0] + 2);                              \
        mma16(acc[1][2], af[1], bf[1] + 0);                              \
        mma16(acc[1][3], af[1], bf[1] + 2);                              \
        LDSM4(af[3][0], af[3][1], af[3][2], af[3][3], ab + aoff[3] + (kb)); \
        mma16(acc[2][0], af[2], bf[0] + 0);                              \
        mma16(acc[2][1], af[2], bf[0] + 2);                              \
        mma16(acc[2][2], af[2], bf[1] + 0);                              \
        mma16(acc[2][3], af[2], bf[1] + 2);                              \
        mma16(acc[3][0], af[3], bf[0] + 0);                              \
        mma16(acc[3][1], af[3], bf[0] + 2);                              \
        mma16(acc[3][2], af[3], bf[1] + 0);                              \
        mma16(acc[3][3], af[3], bf[1] + 2);                              \
    } while (0)

    DN_ISSUE(0, 0);
    DN_ISSUE(1, 64);

    int sC = 0, sP = 2;
    for (int i = 0; i < KI; i++) {
        if (i + 1 < KI) CP_WAITG1(); else CP_WAIT0();
        __syncthreads();
        uint32_t ab = su + (uint32_t)sC * STG;
        sC = (sC == 2) ? 0 : sC + 1;
        DN_STEP(0);
        if (i + 2 < KI) {
            DN_ISSUE(sP, (i + 2) * 64);
            sP = (sP == 2) ? 0 : sP + 1;
        }
        DN_STEP(32);
        DN_STEP(64);
        DN_STEP(96);
    }
#undef DN_ISSUE
#undef DN_STEP

    // epilogue: weighted scatter into buffer (split*2 + slot)
#pragma unroll
    for (int m = 0; m < 4; m++) {
#pragma unroll
        for (int half = 0; half < 2; half++) {
            int R = wm * 64 + m * 16 + gid + half * 8;
            int r = base + R;
            if (r >= cnt) continue;
            int t = g_tok[e * TOKS + r];
            int sl = g_slot[e * TOKS + r];
            float w = g_wt[e * TOKS + r];
            size_t yb = ((size_t)(split * 2 + sl) * TOKS + t) * HDIM + n0;
#pragma unroll
            for (int n = 0; n < 4; n++) {
                int col = wn * 32 + n * 8 + 2 * tig;
                float v0 = acc[m][n][half * 2 + 0], v1 = acc[m][n][half * 2 + 1];
                *reinterpret_cast<float2*>(g_y + yb + col) = make_float2(w * v0, w * v1);
            }
        }
    }
}

// ---------------- combine: out = sum of 4 split/slot buffers ----------------
__global__ void moe_combine(float* __restrict__ out) {
    size_t i = (size_t)blockIdx.x * 256 + threadIdx.x;
    const float4* y0 = reinterpret_cast<const float4*>(g_y);
    const size_t stride = (size_t)TOKS * HDIM / 4;
    float4 a = y0[i], b = y0[i + stride], c = y0[i + 2 * stride], d = y0[i + 3 * stride];
    reinterpret_cast<float4*>(out)[i] =
        make_float4(a.x + b.x + c.x + d.x, a.y + b.y + c.y + d.y,
                    a.z + b.z + c.z + d.z, a.w + b.w + c.w + d.w);
}

// ---------------- launch ----------------
extern "C" void kernel_launch(void* const* d_in, const int* in_sizes, int n_in,
                              void* d_out, int out_size) {
    const float* x   = (const float*)d_in[0];
    const float* wg  = (const float*)d_in[1];
    const float* wgp = (const float*)d_in[2];
    const float* wup = (const float*)d_in[3];
    const float* wdp = (const float*)d_in[4];
    float* out = (float*)d_out;

    cudaFuncSetAttribute(moe_gateup, cudaFuncAttributeMaxDynamicSharedMemorySize, 110592);
    cudaFuncSetAttribute(moe_down,   cudaFuncAttributeMaxDynamicSharedMemorySize, 110592);

    conv_x<<<(TOKS * HDIM / 8) / 256, 256>>>(x);                          // #0 (+ zero g_cnt)
    conv_w3<<<dim3(64, 16, 24), 256>>>(wgp, wup, wdp);                    // #1
    moe_router<<<TOKS / 8, 256>>>(x, wg, out + (size_t)TOKS * HDIM);      // #2
    moe_gateup<<<dim3(FDIM / 64, 20, NEXP), 256, 110592>>>();             // #3
    moe_down<<<dim3(HDIM / 128, 20, NEXP * 2), 256, 110592>>>();          // #4 (split-K=2)
    moe_combine<<<(TOKS * HDIM / 4) / 256, 256>>>(out);                   // #5
}

// round 15
// speedup vs baseline: 1.2672x; 1.0607x over previous
#include <cuda_runtime.h>
#include <cuda_fp16.h>
#include <cstdint>

#define TOKS 8192
#define HDIM 1024
#define FDIM 4096
#define NEXP 8

// ---------------- scratch (__device__ globals; no allocation) ----------------
__device__ int    g_cnt[NEXP];
__device__ int    g_tok[NEXP * TOKS];
__device__ int    g_slot[NEXP * TOKS];
__device__ float  g_wt[NEXP * TOKS];
__device__ __half g_x16[(size_t)TOKS * HDIM];            // fp16 x (16 MB)
__device__ __half g_wg16[(size_t)NEXP * FDIM * HDIM];    // gate W, [e][n][k] (64 MB)
__device__ __half g_wu16[(size_t)NEXP * FDIM * HDIM];    // up   W, [e][n][k] (64 MB)
__device__ __half g_wd16[(size_t)NEXP * HDIM * FDIM];    // down W, [e][n][k] (64 MB)
__device__ __half g_h16[(size_t)2 * TOKS * FDIM];        // hidden (128 MB)
__device__ float  g_y[(size_t)4 * TOKS * HDIM];          // [split][slot] outputs (128 MB)

// ---------------- helpers ----------------
static __device__ __forceinline__ uint32_t smem_u32(const void* p) {
    uint32_t a;
    asm("{ .reg .u64 t; cvta.to.shared.u64 t, %1; cvt.u32.u64 %0, t; }" : "=r"(a) : "l"(p));
    return a;
}
static __device__ __forceinline__ void mma16(float* c, const uint32_t* a, const uint32_t* b) {
    asm volatile(
        "mma.sync.aligned.m16n8k16.row.col.f32.f16.f16.f32 "
        "{%0,%1,%2,%3}, {%4,%5,%6,%7}, {%8,%9}, {%0,%1,%2,%3};"
        : "+f"(c[0]), "+f"(c[1]), "+f"(c[2]), "+f"(c[3])
        : "r"(a[0]), "r"(a[1]), "r"(a[2]), "r"(a[3]), "r"(b[0]), "r"(b[1]));
}
#define LDSM4(r0, r1, r2, r3, addr)                                              \
    asm volatile("ldmatrix.sync.aligned.m8n8.x4.shared.b16 {%0,%1,%2,%3}, [%4];" \
                 : "=r"(r0), "=r"(r1), "=r"(r2), "=r"(r3) : "r"(addr))
#define CP16(dst, src, sz) \
    asm volatile("cp.async.cg.shared.global [%0], [%1], 16, %2;\n" ::"r"(dst), "l"(src), "r"(sz))
#define CP_COMMIT() asm volatile("cp.async.commit_group;\n" ::: "memory")
#define CP_WAITG1() asm volatile("cp.async.wait_group 1;\n" ::: "memory")
#define CP_WAIT0()  asm volatile("cp.async.wait_group 0;\n" ::: "memory")

// mbarrier ring (sm_80 baseline PTX)
#define MBAR_INIT(a, c) asm volatile("mbarrier.init.shared.b64 [%0], %1;" ::"r"(a), "r"(c) : "memory")
#define MBAR_ARRIVE(a)  asm volatile("mbarrier.arrive.shared.b64 _, [%0];" ::"r"(a) : "memory")
#define CPASYNC_MBAR_ARRIVE(a) \
    asm volatile("cp.async.mbarrier.arrive.noinc.shared.b64 [%0];" ::"r"(a) : "memory")
#define MBAR_WAIT(mbar, parity) do {                                                   \
    uint32_t _m = (uint32_t)(mbar);                                                    \
    uint32_t _p = (uint32_t)(parity);                                                  \
    uint32_t _done;                                                                    \
    asm volatile(                                                                      \
        "{\n\t.reg .pred p;\n\t"                                                       \
        "mbarrier.try_wait.parity.shared.b64 p, [%1], %2;\n\t"                         \
        "selp.b32 %0, 1, 0, p;\n\t}"                                                   \
        : "=r"(_done) : "r"(_m), "r"(_p) : "memory");                                  \
    if (!_done) {                                                                      \
        asm volatile(                                                                  \
            "{\n\t.reg .pred P1;\n\t"                                                  \
            "WAIT_LOOP_%=:\n\t"                                                        \
            "mbarrier.try_wait.parity.shared.b64 P1, [%0], %1;\n\t"                    \
            "@P1 bra.uni WAIT_DONE_%=;\n\t"                                            \
            "bra.uni WAIT_LOOP_%=;\n\t"                                                \
            "WAIT_DONE_%=:\n\t}"                                                       \
            :: "r"(_m), "r"(_p) : "memory");                                           \
    }                                                                                  \
} while (0)

static __device__ __forceinline__ float silu(float v) { return v / (1.f + __expf(-v)); }

static __device__ __forceinline__ int expert_off(int e) {
    int off = 0;
#pragma unroll
    for (int i = 0; i < NEXP; i++) if (i < e) off += g_cnt[i];
    return off;
}

// ---------------- convert x -> fp16 (also zeroes g_cnt) ----------------
__global__ void conv_x(const float* __restrict__ x) {
    if (blockIdx.x == 0 && threadIdx.x < NEXP) g_cnt[threadIdx.x] = 0;
    size_t i = ((size_t)blockIdx.x * 256 + threadIdx.x) * 8;
    float4 a = *reinterpret_cast<const float4*>(x + i);
    float4 b = *reinterpret_cast<const float4*>(x + i + 4);
    __half2 h[4];
    h[0] = __floats2half2_rn(a.x, a.y);
    h[1] = __floats2half2_rn(a.z, a.w);
    h[2] = __floats2half2_rn(b.x, b.y);
    h[3] = __floats2half2_rn(b.z, b.w);
    *reinterpret_cast<uint4*>(g_x16 + i) = *reinterpret_cast<uint4*>(h);
}

// ---------------- convert+transpose ALL W: [e][k][n] fp32 -> [e][n][k] fp16 ----------------
__global__ void conv_w3(const float* __restrict__ wgp, const float* __restrict__ wup,
                        const float* __restrict__ wdp) {
    __shared__ float t[64][65];
    int set = blockIdx.z >> 3, e = blockIdx.z & 7;
    const float* src; __half* dst; int Kd, Nd, k0, n0;
    if (set == 0)      { src = wgp; dst = g_wg16; Kd = HDIM; Nd = FDIM; }
    else if (set == 1) { src = wup; dst = g_wu16; Kd = HDIM; Nd = FDIM; }
    else               { src = wdp; dst = g_wd16; Kd = FDIM; Nd = HDIM; }
    if (set < 2) { k0 = blockIdx.y * 64; n0 = blockIdx.x * 64; }
    else         { k0 = blockIdx.x * 64; n0 = blockIdx.y * 64; }

    const float* S = src + ((size_t)e * Kd + k0) * Nd + n0;
    int tid = threadIdx.x;
    int kr = tid >> 4, nc = (tid & 15) * 4;
#pragma unroll
    for (int j = 0; j < 4; j++) {
        float4 v = *reinterpret_cast<const float4*>(S + (size_t)(kr + j * 16) * Nd + nc);
        t[kr + j * 16][nc + 0] = v.x;
        t[kr + j * 16][nc + 1] = v.y;
        t[kr + j * 16][nc + 2] = v.z;
        t[kr + j * 16][nc + 3] = v.w;
    }
    __syncthreads();
    int nr = tid >> 2, kc = (tid & 3) * 16;
    __half hb[16];
#pragma unroll
    for (int q = 0; q < 16; q++) hb[q] = __float2half_rn(t[kc + q][nr]);
    __half* D = dst + ((size_t)e * Nd + n0 + nr) * Kd + k0 + kc;
    *reinterpret_cast<uint4*>(D)     = *reinterpret_cast<uint4*>(hb);
    *reinterpret_cast<uint4*>(D + 8) = *reinterpret_cast<uint4*>(hb + 8);
}

// ---------------- router ----------------
__global__ void moe_router(const float* __restrict__ x, const float* __restrict__ wg,
                           float* __restrict__ logits_out) {
    int t = blockIdx.x * 8 + (threadIdx.x >> 5);
    int lane = threadIdx.x & 31;
    const float* xr = x + (size_t)t * HDIM;
    float acc[8] = {0.f, 0.f, 0.f, 0.f, 0.f, 0.f, 0.f, 0.f};
    for (int j = lane; j < HDIM; j += 32) {
        float xv = xr[j];
        const float4* w4 = reinterpret_cast<const float4*>(wg + (size_t)j * NEXP);
        float4 a = w4[0], b = w4[1];
        acc[0] += xv * a.x; acc[1] += xv * a.y; acc[2] += xv * a.z; acc[3] += xv * a.w;
        acc[4] += xv * b.x; acc[5] += xv * b.y; acc[6] += xv * b.z; acc[7] += xv * b.w;
    }
#pragma unroll
    for (int o = 16; o > 0; o >>= 1)
#pragma unroll
        for (int k = 0; k < 8; k++) acc[k] += __shfl_xor_sync(0xffffffffu, acc[k], o);

    if (lane == 0) {
#pragma unroll
        for (int k = 0; k < 8; k++) logits_out[(size_t)t * NEXP + k] = acc[k];
        int i0 = 0; float v0 = acc[0];
#pragma unroll
        for (int k = 1; k < 8; k++) if (acc[k] > v0) { v0 = acc[k]; i0 = k; }
        int i1 = -1; float v1 = -3.4e38f;
#pragma unroll
        for (int k = 0; k < 8; k++) if (k != i0 && acc[k] > v1) { v1 = acc[k]; i1 = k; }
        float w0 = 1.f / (1.f + __expf(v1 - v0));
        float w1 = 1.f - w0;
        int p0 = atomicAdd(&g_cnt[i0], 1);
        g_tok[i0 * TOKS + p0] = t; g_slot[i0 * TOKS + p0] = 0; g_wt[i0 * TOKS + p0] = w0;
        int p1 = atomicAdd(&g_cnt[i1], 1);
        g_tok[i1 * TOKS + p1] = t; g_slot[i1 * TOKS + p1] = 1; g_wt[i1 * TOKS + p1] = w1;
    }
}

// ---------------- fused gate+up GEMM: mbarrier producer/consumer ring ----------------
// BM=128, BN=64/side, BK=64, pitch 72 halves. 3 stages @36864B + 48B barriers = 110640B.
// full[s]: 256 cp.async.noinc arrivals; empty[s]: 256 thread arrivals. No __syncthreads
// in the mainloop; warps decouple by up to a full tile.
__global__ void __launch_bounds__(256, 2)
moe_gateup() {
    int e = blockIdx.z;
    int cnt = g_cnt[e];
    int base = blockIdx.y * 128;
    if (base >= cnt) return;
    int n0 = blockIdx.x * 64;
    int off = expert_off(e);
    const __half* wge = g_wg16 + (size_t)e * FDIM * HDIM;
    const __half* wue = g_wu16 + (size_t)e * FDIM * HDIM;

    extern __shared__ char smem8[];
    uint32_t su = smem_u32(smem8);
    const uint32_t STG = 36864;
    const uint32_t MB_FULL = 110592, MB_EMPTY = 110616;

    int tid = threadIdx.x, lane = tid & 31;
    int gid = lane >> 2, tig = lane & 3;
    int wid = tid >> 5, wm = wid >> 2, wn = wid & 3;

    if (tid < 3) {
        MBAR_INIT(su + MB_FULL + tid * 8, 256);
        MBAR_INIT(su + MB_EMPTY + tid * 8, 256);
    }

    const __half* asrc[4]; uint32_t asz[4], adst[4];
#pragma unroll
    for (int j = 0; j < 4; j++) {
        int idx = tid + j * 256;
        int row = idx >> 3, c = idx & 7;
        int r = base + row;
        bool v = r < cnt;
        int tok = v ? g_tok[e * TOKS + r] : 0;
        asrc[j] = g_x16 + (size_t)tok * HDIM + c * 8;
        asz[j] = v ? 16u : 0u;
        adst[j] = (uint32_t)(row * 144 + c * 16);
    }
    const __half* gsrc[2]; const __half* usrc[2]; uint32_t bdst[2];
#pragma unroll
    for (int j = 0; j < 2; j++) {
        int idx = tid + j * 256;
        int n = idx >> 3, c = idx & 7;
        gsrc[j] = wge + (size_t)(n0 + n) * HDIM + c * 8;
        usrc[j] = wue + (size_t)(n0 + n) * HDIM + c * 8;
        bdst[j] = (uint32_t)(n * 144 + c * 16);
    }

    uint32_t aoff[4];
#pragma unroll
    for (int m = 0; m < 4; m++)
        aoff[m] = (uint32_t)(((wm * 64 + m * 16 + (lane & 15)) * 72 + (lane >> 4) * 8) * 2);
    uint32_t boff = (uint32_t)(((wn * 16 + (lane & 7) + ((lane >> 4) & 1) * 8) * 72 +
                                ((lane >> 3) & 1) * 8) * 2);

    float accG[4][2][4], accU[4][2][4];
#pragma unroll
    for (int m = 0; m < 4; m++)
#pragma unroll
        for (int n = 0; n < 2; n++)
#pragma unroll
            for (int q = 0; q < 4; q++) { accG[m][n][q] = 0.f; accU[m][n][q] = 0.f; }

    const int KI = HDIM / 64;  // 16

#define GU_CP(s, k0)                                                     \
    do {                                                                 \
        uint32_t abw = su + (uint32_t)(s) * STG;                         \
        _Pragma("unroll") for (int j = 0; j < 4; j++)                    \
            CP16(abw + adst[j], asrc[j] + (k0), asz[j]);                 \
        _Pragma("unroll") for (int j = 0; j < 2; j++)                    \
            CP16(abw + 18432u + bdst[j], gsrc[j] + (k0), 16u);           \
        _Pragma("unroll") for (int j = 0; j < 2; j++)                    \
            CP16(abw + 27648u + bdst[j], usrc[j] + (k0), 16u);           \
    } while (0)

#define GU_STEP(kb)                                                      \
    do {                                                                 \
        uint32_t af[4][4], bg[4], bu[4];                                 \
        LDSM4(bg[0], bg[1], bg[2], bg[3], ab + 18432u + boff + (kb));    \
        LDSM4(af[0][0], af[0][1], af[0][2], af[0][3], ab + aoff[0] + (kb)); \
        LDSM4(bu[0], bu[1], bu[2], bu[3], ab + 27648u + boff + (kb));    \
        LDSM4(af[1][0], af[1][1], af[1][2], af[1][3], ab + aoff[1] + (kb)); \
        mma16(accG[0][0], af[0], bg + 0);                                \
        mma16(accG[0][1], af[0], bg + 2);                                \
        mma16(accU[0][0], af[0], bu + 0);                                \
        mma16(accU[0][1], af[0], bu + 2);                                \
        LDSM4(af[2][0], af[2][1], af[2][2], af[2][3], ab + aoff[2] + (kb)); \
        mma16(accG[1][0], af[1], bg + 0);                                \
        mma16(accG[1][1], af[1], bg + 2);                                \
        mma16(accU[1][0], af[1], bu + 0);                                \
        mma16(accU[1][1], af[1], bu + 2);                                \
        LDSM4(af[3][0], af[3][1], af[3][2], af[3][3], ab + aoff[3] + (kb)); \
        mma16(accG[2][0], af[2], bg + 0);                                \
        mma16(accG[2][1], af[2], bg + 2);                                \
        mma16(accU[2][0], af[2], bu + 0);                                \
        mma16(accU[2][1], af[2], bu + 2);                                \
        mma16(accG[3][0], af[3], bg + 0);                                \
        mma16(accG[3][1], af[3], bg + 2);                                \
        mma16(accU[3][0], af[3], bu + 0);                                \
        mma16(accU[3][1], af[3], bu + 2);                                \
    } while (0)

    __syncthreads();  // barrier init visible before any async arrive targets them

    // prefill stage 0 and 1 (first fills: no empty wait)
    GU_CP(0, 0);  CPASYNC_MBAR_ARRIVE(su + MB_FULL + 0 * 8);
    GU_CP(1, 64); CPASYNC_MBAR_ARRIVE(su + MB_FULL + 1 * 8);

    int phF0 = 0, phF1 = 0, phF2 = 0;
    int phE0 = 0, phE1 = 0, phE2 = 0;
    int sC = 0, sP = 2;
    for (int i = 0; i < KI; i++) {
        int s = sC;
        sC = (sC == 2) ? 0 : sC + 1;
        int ph = (s == 0) ? phF0 : (s == 1) ? phF1 : phF2;
        MBAR_WAIT(su + MB_FULL + s * 8, ph);
        if (s == 0) phF0 ^= 1; else if (s == 1) phF1 ^= 1; else phF2 ^= 1;
        uint32_t ab = su + (uint32_t)s * STG;
        GU_STEP(0);
        if (i + 2 < KI) {
            int sc = sP;
            sP = (sP == 2) ? 0 : sP + 1;
            if (i > 0) {  // first fill of stage 2 (i==0) needs no empty wait
                int pe = (sc == 0) ? phE0 : (sc == 1) ? phE1 : phE2;
                MBAR_WAIT(su + MB_EMPTY + sc * 8, pe);
                if (sc == 0) phE0 ^= 1; else if (sc == 1) phE1 ^= 1; else phE2 ^= 1;
            }
            GU_CP(sc, (i + 2) * 64);
            CPASYNC_MBAR_ARRIVE(su + MB_FULL + sc * 8);
        }
        GU_STEP(32);
        GU_STEP(64);
        GU_STEP(96);
        MBAR_ARRIVE(su + MB_EMPTY + s * 8);
    }
#undef GU_CP
#undef GU_STEP

    // epilogue: g_h16 = fp16(silu(g) * u)
#pragma unroll
    for (int m = 0; m < 4; m++) {
#pragma unroll
        for (int half = 0; half < 2; half++) {
            int R = wm * 64 + m * 16 + gid + half * 8;
            int r = base + R;
            if (r >= cnt) continue;
            size_t rb = (size_t)(off + r) * FDIM + n0;
#pragma unroll
            for (int n = 0; n < 2; n++) {
                int col = wn * 16 + n * 8 + 2 * tig;
                float h0 = silu(accG[m][n][half * 2 + 0]) * accU[m][n][half * 2 + 0];
                float h1 = silu(accG[m][n][half * 2 + 1]) * accU[m][n][half * 2 + 1];
                *reinterpret_cast<__half2*>(g_h16 + rb + col) = __floats2half2_rn(h0, h1);
            }
        }
    }
}

// ---------------- down GEMM, split-K=2 (unchanged proven path) ----------------
__global__ void __launch_bounds__(256, 2)
moe_down() {
    int e = blockIdx.z & 7;
    int split = blockIdx.z >> 3;
    int cnt = g_cnt[e];
    int base = blockIdx.y * 128;
    if (base >= cnt) return;
    int n0 = blockIdx.x * 128;
    int off = expert_off(e);
    int kbase = split * (FDIM / 2);
    const __half* wde = g_wd16 + (size_t)e * HDIM * FDIM;

    extern __shared__ char smem8[];
    uint32_t su = smem_u32(smem8);
    const uint32_t STG = 36864;

    int tid = threadIdx.x, lane = tid & 31;
    int gid = lane >> 2, tig = lane & 3;
    int wid = tid >> 5, wm = wid >> 2, wn = wid & 3;

    const __half* asrc[4]; uint32_t asz[4], adst[4];
#pragma unroll
    for (int j = 0; j < 4; j++) {
        int idx = tid + j * 256;
        int row = idx >> 3, c = idx & 7;
        int r = base + row;
        bool v = r < cnt;
        size_t arow = v ? (size_t)(off + r) : 0;
        asrc[j] = g_h16 + arow * FDIM + kbase + c * 8;
        asz[j] = v ? 16u : 0u;
        adst[j] = (uint32_t)(row * 144 + c * 16);
    }
    const __half* bsrc[4]; uint32_t bdst[4];
#pragma unroll
    for (int j = 0; j < 4; j++) {
        int idx = tid + j * 256;
        int n = idx >> 3, c = idx & 7;
        bsrc[j] = wde + (size_t)(n0 + n) * FDIM + kbase + c * 8;
        bdst[j] = (uint32_t)(n * 144 + c * 16);
    }

    uint32_t aoff[4];
#pragma unroll
    for (int m = 0; m < 4; m++)
        aoff[m] = (uint32_t)(((wm * 64 + m * 16 + (lane & 15)) * 72 + (lane >> 4) * 8) * 2);
    uint32_t boff[2];
#pragma unroll
    for (int p = 0; p < 2; p++)
        boff[p] = (uint32_t)(((wn * 32 + p * 16 + (lane & 7) + ((lane >> 4) & 1) * 8) * 72 +
                              ((lane >> 3) & 1) * 8) * 2);

    float acc[4][4][4];
#pragma unroll
    for (int m = 0; m < 4; m++)
#pragma unroll
        for (int n = 0; n < 4; n++)
#pragma unroll
            for (int q = 0; q < 4; q++) acc[m][n][q] = 0.f;

    const int KI = FDIM / 128;  // 32 tiles per split

#define DN_ISSUE(s, k0)                                                  \
    do {                                                                 \
        uint32_t abw = su + (uint32_t)(s) * STG;                         \
        _Pragma("unroll") for (int j = 0; j < 4; j++)                    \
            CP16(abw + adst[j], asrc[j] + (k0), asz[j]);                 \
        _Pragma("unroll") for (int j = 0; j < 4; j++)                    \
            CP16(abw + 18432u + bdst[j], bsrc[j] + (k0), 16u);           \
        CP_COMMIT();                                                     \
    } while (0)

#define DN_STEP(kb)                                                      \
    do {                                                                 \
        uint32_t af[4][4], bf[2][4];                                     \
        LDSM4(bf[0][0], bf[0][1], bf[0][2], bf[0][3], ab + 18432u + boff[0] + (kb)); \
        LDSM4(af[0][0], af[0][1], af[0][2], af[0][3], ab + aoff[0] + (kb)); \
        LDSM4(bf[1][0], bf[1][1], bf[1][2], bf[1][3], ab + 18432u + boff[1] + (kb)); \
        LDSM4(af[1][0], af[1][1], af[1][2], af[1][3], ab + aoff[1] + (kb)); \
        mma16(acc[0][0], af[0], bf[0] + 0);                              \
        mma16(acc[0][1], af[0], bf[0] + 2);                              \
        mma16(acc[0][2], af[0], bf[1] + 0);                              \
        mma16(acc[0][3], af[0], bf[1] + 2);                              \
        LDSM4(af[2][0], af[2][1], af[2][2], af[2][3], ab + aoff[2] + (kb)); \
        mma16(acc[1][0], af[1], bf[0] + 0);                              \
        mma16(acc[1][1], af[1], bf[0] + 2);                              \
        mma16(acc[1][2], af[1], bf[1] + 0);                              \
        mma16(acc[1][3], af[1], bf[1] + 2);                              \
        LDSM4(af[3][0], af[3][1], af[3][2], af[3][3], ab + aoff[3] + (kb)); \
        mma16(acc[2][0], af[2], bf[0] + 0);                              \
        mma16(acc[2][1], af[2], bf[0] + 2);                              \
        mma16(acc[2][2], af[2], bf[1] + 0);                              \
        mma16(acc[2][3], af[2], bf[1] + 2);                              \
        mma16(acc[3][0], af[3], bf[0] + 0);                              \
        mma16(acc[3][1], af[3], bf[0] + 2);                              \
        mma16(acc[3][2], af[3], bf[1] + 0);                              \
        mma16(acc[3][3], af[3], bf[1] + 2);                              \
    } while (0)

    DN_ISSUE(0, 0);
    DN_ISSUE(1, 64);

    int sC = 0, sP = 2;
    for (int i = 0; i < KI; i++) {
        if (i + 1 < KI) CP_WAITG1(); else CP_WAIT0();
        __syncthreads();
        uint32_t ab = su + (uint32_t)sC * STG;
        sC = (sC == 2) ? 0 : sC + 1;
        DN_STEP(0);
        if (i + 2 < KI) {
            DN_ISSUE(sP, (i + 2) * 64);
            sP = (sP == 2) ? 0 : sP + 1;
        }
        DN_STEP(32);
        DN_STEP(64);
        DN_STEP(96);
    }
#undef DN_ISSUE
#undef DN_STEP

    // epilogue: weighted scatter into buffer (split*2 + slot)
#pragma unroll
    for (int m = 0; m < 4; m++) {
#pragma unroll
        for (int half = 0; half < 2; half++) {
            int R = wm * 64 + m * 16 + gid + half * 8;
            int r = base + R;
            if (r >= cnt) continue;
            int t = g_tok[e * TOKS + r];
            int sl = g_slot[e * TOKS + r];
            float w = g_wt[e * TOKS + r];
            size_t yb = ((size_t)(split * 2 + sl) * TOKS + t) * HDIM + n0;
#pragma unroll
            for (int n = 0; n < 4; n++) {
                int col = wn * 32 + n * 8 + 2 * tig;
                float v0 = acc[m][n][half * 2 + 0], v1 = acc[m][n][half * 2 + 1];
                *reinterpret_cast<float2*>(g_y + yb + col) = make_float2(w * v0, w * v1);
            }
        }
    }
}

// ---------------- combine: out = sum of 4 split/slot buffers ----------------
__global__ void moe_combine(float* __restrict__ out) {
    size_t i = (size_t)blockIdx.x * 256 + threadIdx.x;
    const float4* y0 = reinterpret_cast<const float4*>(g_y);
    const size_t stride = (size_t)TOKS * HDIM / 4;
    float4 a = y0[i], b = y0[i + stride], c = y0[i + 2 * stride], d = y0[i + 3 * stride];
    reinterpret_cast<float4*>(out)[i] =
        make_float4(a.x + b.x + c.x + d.x, a.y + b.y + c.y + d.y,
                    a.z + b.z + c.z + d.z, a.w + b.w + c.w + d.w);
}

// ---------------- launch ----------------
extern "C" void kernel_launch(void* const* d_in, const int* in_sizes, int n_in,
                              void* d_out, int out_size) {
    const float* x   = (const float*)d_in[0];
    const float* wg  = (const float*)d_in[1];
    const float* wgp = (const float*)d_in[2];
    const float* wup = (const float*)d_in[3];
    const float* wdp = (const float*)d_in[4];
    float* out = (float*)d_out;

    cudaFuncSetAttribute(moe_gateup, cudaFuncAttributeMaxDynamicSharedMemorySize, 110640);
    cudaFuncSetAttribute(moe_down,   cudaFuncAttributeMaxDynamicSharedMemorySize, 110592);

    conv_x<<<(TOKS * HDIM / 8) / 256, 256>>>(x);                          // #0 (+ zero g_cnt)
    conv_w3<<<dim3(64, 16, 24), 256>>>(wgp, wup, wdp);                    // #1
    moe_router<<<TOKS / 8, 256>>>(x, wg, out + (size_t)TOKS * HDIM);      // #2
    moe_gateup<<<dim3(FDIM / 64, 20, NEXP), 256, 110640>>>();             // #3 (mbarrier ring)
    moe_down<<<dim3(HDIM / 128, 20, NEXP * 2), 256, 110592>>>();          // #4 (split-K=2)
    moe_combine<<<(TOKS * HDIM / 4) / 256, 256>>>(out);                   // #5
}

// round 16
// speedup vs baseline: 1.2886x; 1.0169x over previous
#include <cuda_runtime.h>
#include <cuda_fp16.h>
#include <cstdint>

#define TOKS 8192
#define HDIM 1024
#define FDIM 4096
#define NEXP 8

// ---------------- scratch (__device__ globals; no allocation) ----------------
__device__ int    g_cnt[NEXP];
__device__ int    g_tok[NEXP * TOKS];
__device__ int    g_slot[NEXP * TOKS];
__device__ float  g_wt[NEXP * TOKS];
__device__ __half g_x16[(size_t)TOKS * HDIM];            // fp16 x (16 MB)
__device__ __half g_wg16[(size_t)NEXP * FDIM * HDIM];    // gate W, [e][n][k] (64 MB)
__device__ __half g_wu16[(size_t)NEXP * FDIM * HDIM];    // up   W, [e][n][k] (64 MB)
__device__ __half g_wd16[(size_t)NEXP * HDIM * FDIM];    // down W, [e][n][k] (64 MB)
__device__ __half g_h16[(size_t)2 * TOKS * FDIM];        // hidden (128 MB)
__device__ float  g_y[(size_t)4 * TOKS * HDIM];          // [split][slot] outputs (128 MB)

// ---------------- helpers ----------------
static __device__ __forceinline__ uint32_t smem_u32(const void* p) {
    uint32_t a;
    asm("{ .reg .u64 t; cvta.to.shared.u64 t, %1; cvt.u32.u64 %0, t; }" : "=r"(a) : "l"(p));
    return a;
}
static __device__ __forceinline__ void mma16(float* c, const uint32_t* a, const uint32_t* b) {
    asm volatile(
        "mma.sync.aligned.m16n8k16.row.col.f32.f16.f16.f32 "
        "{%0,%1,%2,%3}, {%4,%5,%6,%7}, {%8,%9}, {%0,%1,%2,%3};"
        : "+f"(c[0]), "+f"(c[1]), "+f"(c[2]), "+f"(c[3])
        : "r"(a[0]), "r"(a[1]), "r"(a[2]), "r"(a[3]), "r"(b[0]), "r"(b[1]));
}
#define LDSM4(r0, r1, r2, r3, addr)                                              \
    asm volatile("ldmatrix.sync.aligned.m8n8.x4.shared.b16 {%0,%1,%2,%3}, [%4];" \
                 : "=r"(r0), "=r"(r1), "=r"(r2), "=r"(r3) : "r"(addr))
#define CP16(dst, src, sz) \
    asm volatile("cp.async.cg.shared.global [%0], [%1], 16, %2;\n" ::"r"(dst), "l"(src), "r"(sz))

// mbarrier ring (sm_80 baseline PTX)
#define MBAR_INIT(a, c) asm volatile("mbarrier.init.shared.b64 [%0], %1;" ::"r"(a), "r"(c) : "memory")
#define MBAR_ARRIVE(a)  asm volatile("mbarrier.arrive.shared.b64 _, [%0];" ::"r"(a) : "memory")
#define CPASYNC_MBAR_ARRIVE(a) \
    asm volatile("cp.async.mbarrier.arrive.noinc.shared.b64 [%0];" ::"r"(a) : "memory")
#define MBAR_WAIT(mbar, parity) do {                                                   \
    uint32_t _m = (uint32_t)(mbar);                                                    \
    uint32_t _p = (uint32_t)(parity);                                                  \
    uint32_t _done;                                                                    \
    asm volatile(                                                                      \
        "{\n\t.reg .pred p;\n\t"                                                       \
        "mbarrier.try_wait.parity.shared.b64 p, [%1], %2;\n\t"                         \
        "selp.b32 %0, 1, 0, p;\n\t}"                                                   \
        : "=r"(_done) : "r"(_m), "r"(_p) : "memory");                                  \
    if (!_done) {                                                                      \
        asm volatile(                                                                  \
            "{\n\t.reg .pred P1;\n\t"                                                  \
            "WAIT_LOOP_%=:\n\t"                                                        \
            "mbarrier.try_wait.parity.shared.b64 P1, [%0], %1;\n\t"                    \
            "@P1 bra.uni WAIT_DONE_%=;\n\t"                                            \
            "bra.uni WAIT_LOOP_%=;\n\t"                                                \
            "WAIT_DONE_%=:\n\t}"                                                       \
            :: "r"(_m), "r"(_p) : "memory");                                           \
    }                                                                                  \
} while (0)

static __device__ __forceinline__ float silu(float v) { return v / (1.f + __expf(-v)); }

static __device__ __forceinline__ int expert_off(int e) {
    int off = 0;
#pragma unroll
    for (int i = 0; i < NEXP; i++) if (i < e) off += g_cnt[i];
    return off;
}

// ---------------- convert x -> fp16 (also zeroes g_cnt) ----------------
__global__ void conv_x(const float* __restrict__ x) {
    if (blockIdx.x == 0 && threadIdx.x < NEXP) g_cnt[threadIdx.x] = 0;
    size_t i = ((size_t)blockIdx.x * 256 + threadIdx.x) * 8;
    float4 a = *reinterpret_cast<const float4*>(x + i);
    float4 b = *reinterpret_cast<const float4*>(x + i + 4);
    __half2 h[4];
    h[0] = __floats2half2_rn(a.x, a.y);
    h[1] = __floats2half2_rn(a.z, a.w);
    h[2] = __floats2half2_rn(b.x, b.y);
    h[3] = __floats2half2_rn(b.z, b.w);
    *reinterpret_cast<uint4*>(g_x16 + i) = *reinterpret_cast<uint4*>(h);
}

// ---------------- convert+transpose ALL W: [e][k][n] fp32 -> [e][n][k] fp16 ----------------
__global__ void conv_w3(const float* __restrict__ wgp, const float* __restrict__ wup,
                        const float* __restrict__ wdp) {
    __shared__ float t[64][65];
    int set = blockIdx.z >> 3, e = blockIdx.z & 7;
    const float* src; __half* dst; int Kd, Nd, k0, n0;
    if (set == 0)      { src = wgp; dst = g_wg16; Kd = HDIM; Nd = FDIM; }
    else if (set == 1) { src = wup; dst = g_wu16; Kd = HDIM; Nd = FDIM; }
    else               { src = wdp; dst = g_wd16; Kd = FDIM; Nd = HDIM; }
    if (set < 2) { k0 = blockIdx.y * 64; n0 = blockIdx.x * 64; }
    else         { k0 = blockIdx.x * 64; n0 = blockIdx.y * 64; }

    const float* S = src + ((size_t)e * Kd + k0) * Nd + n0;
    int tid = threadIdx.x;
    int kr = tid >> 4, nc = (tid & 15) * 4;
#pragma unroll
    for (int j = 0; j < 4; j++) {
        float4 v = *reinterpret_cast<const float4*>(S + (size_t)(kr + j * 16) * Nd + nc);
        t[kr + j * 16][nc + 0] = v.x;
        t[kr + j * 16][nc + 1] = v.y;
        t[kr + j * 16][nc + 2] = v.z;
        t[kr + j * 16][nc + 3] = v.w;
    }
    __syncthreads();
    int nr = tid >> 2, kc = (tid & 3) * 16;
    __half hb[16];
#pragma unroll
    for (int q = 0; q < 16; q++) hb[q] = __float2half_rn(t[kc + q][nr]);
    __half* D = dst + ((size_t)e * Nd + n0 + nr) * Kd + k0 + kc;
    *reinterpret_cast<uint4*>(D)     = *reinterpret_cast<uint4*>(hb);
    *reinterpret_cast<uint4*>(D + 8) = *reinterpret_cast<uint4*>(hb + 8);
}

// ---------------- router ----------------
__global__ void moe_router(const float* __restrict__ x, const float* __restrict__ wg,
                           float* __restrict__ logits_out) {
    int t = blockIdx.x * 8 + (threadIdx.x >> 5);
    int lane = threadIdx.x & 31;
    const float* xr = x + (size_t)t * HDIM;
    float acc[8] = {0.f, 0.f, 0.f, 0.f, 0.f, 0.f, 0.f, 0.f};
    for (int j = lane; j < HDIM; j += 32) {
        float xv = xr[j];
        const float4* w4 = reinterpret_cast<const float4*>(wg + (size_t)j * NEXP);
        float4 a = w4[0], b = w4[1];
        acc[0] += xv * a.x; acc[1] += xv * a.y; acc[2] += xv * a.z; acc[3] += xv * a.w;
        acc[4] += xv * b.x; acc[5] += xv * b.y; acc[6] += xv * b.z; acc[7] += xv * b.w;
    }
#pragma unroll
    for (int o = 16; o > 0; o >>= 1)
#pragma unroll
        for (int k = 0; k < 8; k++) acc[k] += __shfl_xor_sync(0xffffffffu, acc[k], o);

    if (lane == 0) {
#pragma unroll
        for (int k = 0; k < 8; k++) logits_out[(size_t)t * NEXP + k] = acc[k];
        int i0 = 0; float v0 = acc[0];
#pragma unroll
        for (int k = 1; k < 8; k++) if (acc[k] > v0) { v0 = acc[k]; i0 = k; }
        int i1 = -1; float v1 = -3.4e38f;
#pragma unroll
        for (int k = 0; k < 8; k++) if (k != i0 && acc[k] > v1) { v1 = acc[k]; i1 = k; }
        float w0 = 1.f / (1.f + __expf(v1 - v0));
        float w1 = 1.f - w0;
        int p0 = atomicAdd(&g_cnt[i0], 1);
        g_tok[i0 * TOKS + p0] = t; g_slot[i0 * TOKS + p0] = 0; g_wt[i0 * TOKS + p0] = w0;
        int p1 = atomicAdd(&g_cnt[i1], 1);
        g_tok[i1 * TOKS + p1] = t; g_slot[i1 * TOKS + p1] = 1; g_wt[i1 * TOKS + p1] = w1;
    }
}

// ---------------- fused gate+up GEMM: mbarrier producer/consumer ring ----------------
// BM=128, BN=64/side, BK=64, pitch 72 halves. 3 stages @36864B + 48B barriers = 110640B.
__global__ void __launch_bounds__(256, 2)
moe_gateup() {
    int e = blockIdx.z;
    int cnt = g_cnt[e];
    int base = blockIdx.y * 128;
    if (base >= cnt) return;
    int n0 = blockIdx.x * 64;
    int off = expert_off(e);
    const __half* wge = g_wg16 + (size_t)e * FDIM * HDIM;
    const __half* wue = g_wu16 + (size_t)e * FDIM * HDIM;

    extern __shared__ char smem8[];
    uint32_t su = smem_u32(smem8);
    const uint32_t STG = 36864;
    const uint32_t MB_FULL = 110592, MB_EMPTY = 110616;

    int tid = threadIdx.x, lane = tid & 31;
    int gid = lane >> 2, tig = lane & 3;
    int wid = tid >> 5, wm = wid >> 2, wn = wid & 3;

    if (tid < 3) {
        MBAR_INIT(su + MB_FULL + tid * 8, 256);
        MBAR_INIT(su + MB_EMPTY + tid * 8, 256);
    }

    const __half* asrc[4]; uint32_t asz[4], adst[4];
#pragma unroll
    for (int j = 0; j < 4; j++) {
        int idx = tid + j * 256;
        int row = idx >> 3, c = idx & 7;
        int r = base + row;
        bool v = r < cnt;
        int tok = v ? g_tok[e * TOKS + r] : 0;
        asrc[j] = g_x16 + (size_t)tok * HDIM + c * 8;
        asz[j] = v ? 16u : 0u;
        adst[j] = (uint32_t)(row * 144 + c * 16);
    }
    const __half* gsrc[2]; const __half* usrc[2]; uint32_t bdst[2];
#pragma unroll
    for (int j = 0; j < 2; j++) {
        int idx = tid + j * 256;
        int n = idx >> 3, c = idx & 7;
        gsrc[j] = wge + (size_t)(n0 + n) * HDIM + c * 8;
        usrc[j] = wue + (size_t)(n0 + n) * HDIM + c * 8;
        bdst[j] = (uint32_t)(n * 144 + c * 16);
    }

    uint32_t aoff[4];
#pragma unroll
    for (int m = 0; m < 4; m++)
        aoff[m] = (uint32_t)(((wm * 64 + m * 16 + (lane & 15)) * 72 + (lane >> 4) * 8) * 2);
    uint32_t boff = (uint32_t)(((wn * 16 + (lane & 7) + ((lane >> 4) & 1) * 8) * 72 +
                                ((lane >> 3) & 1) * 8) * 2);

    float accG[4][2][4], accU[4][2][4];
#pragma unroll
    for (int m = 0; m < 4; m++)
#pragma unroll
        for (int n = 0; n < 2; n++)
#pragma unroll
            for (int q = 0; q < 4; q++) { accG[m][n][q] = 0.f; accU[m][n][q] = 0.f; }

    const int KI = HDIM / 64;  // 16

#define GU_CP(s, k0)                                                     \
    do {                                                                 \
        uint32_t abw = su + (uint32_t)(s) * STG;                         \
        _Pragma("unroll") for (int j = 0; j < 4; j++)                    \
            CP16(abw + adst[j], asrc[j] + (k0), asz[j]);                 \
        _Pragma("unroll") for (int j = 0; j < 2; j++)                    \
            CP16(abw + 18432u + bdst[j], gsrc[j] + (k0), 16u);           \
        _Pragma("unroll") for (int j = 0; j < 2; j++)                    \
            CP16(abw + 27648u + bdst[j], usrc[j] + (k0), 16u);           \
    } while (0)

#define GU_STEP(kb)                                                      \
    do {                                                                 \
        uint32_t af[4][4], bg[4], bu[4];                                 \
        LDSM4(bg[0], bg[1], bg[2], bg[3], ab + 18432u + boff + (kb));    \
        LDSM4(af[0][0], af[0][1], af[0][2], af[0][3], ab + aoff[0] + (kb)); \
        LDSM4(bu[0], bu[1], bu[2], bu[3], ab + 27648u + boff + (kb));    \
        LDSM4(af[1][0], af[1][1], af[1][2], af[1][3], ab + aoff[1] + (kb)); \
        mma16(accG[0][0], af[0], bg + 0);                                \
        mma16(accG[0][1], af[0], bg + 2);                                \
        mma16(accU[0][0], af[0], bu + 0);                                \
        mma16(accU[0][1], af[0], bu + 2);                                \
        LDSM4(af[2][0], af[2][1], af[2][2], af[2][3], ab + aoff[2] + (kb)); \
        mma16(accG[1][0], af[1], bg + 0);                                \
        mma16(accG[1][1], af[1], bg + 2);                                \
        mma16(accU[1][0], af[1], bu + 0);                                \
        mma16(accU[1][1], af[1], bu + 2);                                \
        LDSM4(af[3][0], af[3][1], af[3][2], af[3][3], ab + aoff[3] + (kb)); \
        mma16(accG[2][0], af[2], bg + 0);                                \
        mma16(accG[2][1], af[2], bg + 2);                                \
        mma16(accU[2][0], af[2], bu + 0);                                \
        mma16(accU[2][1], af[2], bu + 2);                                \
        mma16(accG[3][0], af[3], bg + 0);                                \
        mma16(accG[3][1], af[3], bg + 2);                                \
        mma16(accU[3][0], af[3], bu + 0);                                \
        mma16(accU[3][1], af[3], bu + 2);                                \
    } while (0)

    __syncthreads();  // barrier init visible before any async arrive targets them

    GU_CP(0, 0);  CPASYNC_MBAR_ARRIVE(su + MB_FULL + 0 * 8);
    GU_CP(1, 64); CPASYNC_MBAR_ARRIVE(su + MB_FULL + 1 * 8);

    int phF0 = 0, phF1 = 0, phF2 = 0;
    int phE0 = 0, phE1 = 0, phE2 = 0;
    int sC = 0, sP = 2;
    for (int i = 0; i < KI; i++) {
        int s = sC;
        sC = (sC == 2) ? 0 : sC + 1;
        int ph = (s == 0) ? phF0 : (s == 1) ? phF1 : phF2;
        MBAR_WAIT(su + MB_FULL + s * 8, ph);
        if (s == 0) phF0 ^= 1; else if (s == 1) phF1 ^= 1; else phF2 ^= 1;
        uint32_t ab = su + (uint32_t)s * STG;
        GU_STEP(0);
        if (i + 2 < KI) {
            int sc = sP;
            sP = (sP == 2) ? 0 : sP + 1;
            if (i > 0) {
                int pe = (sc == 0) ? phE0 : (sc == 1) ? phE1 : phE2;
                MBAR_WAIT(su + MB_EMPTY + sc * 8, pe);
                if (sc == 0) phE0 ^= 1; else if (sc == 1) phE1 ^= 1; else phE2 ^= 1;
            }
            GU_CP(sc, (i + 2) * 64);
            CPASYNC_MBAR_ARRIVE(su + MB_FULL + sc * 8);
        }
        GU_STEP(32);
        GU_STEP(64);
        GU_STEP(96);
        MBAR_ARRIVE(su + MB_EMPTY + s * 8);
    }
#undef GU_CP
#undef GU_STEP

    // epilogue: g_h16 = fp16(silu(g) * u)
#pragma unroll
    for (int m = 0; m < 4; m++) {
#pragma unroll
        for (int half = 0; half < 2; half++) {
            int R = wm * 64 + m * 16 + gid + half * 8;
            int r = base + R;
            if (r >= cnt) continue;
            size_t rb = (size_t)(off + r) * FDIM + n0;
#pragma unroll
            for (int n = 0; n < 2; n++) {
                int col = wn * 16 + n * 8 + 2 * tig;
                float h0 = silu(accG[m][n][half * 2 + 0]) * accU[m][n][half * 2 + 0];
                float h1 = silu(accG[m][n][half * 2 + 1]) * accU[m][n][half * 2 + 1];
                *reinterpret_cast<__half2*>(g_h16 + rb + col) = __floats2half2_rn(h0, h1);
            }
        }
    }
}

// ---------------- down GEMM, split-K=2, mbarrier ring ----------------
// Same ring structure as gateup; stage layout A@0 (18432B) + B@18432 (18432B).
__global__ void __launch_bounds__(256, 2)
moe_down() {
    int e = blockIdx.z & 7;
    int split = blockIdx.z >> 3;
    int cnt = g_cnt[e];
    int base = blockIdx.y * 128;
    if (base >= cnt) return;
    int n0 = blockIdx.x * 128;
    int off = expert_off(e);
    int kbase = split * (FDIM / 2);
    const __half* wde = g_wd16 + (size_t)e * HDIM * FDIM;

    extern __shared__ char smem8[];
    uint32_t su = smem_u32(smem8);
    const uint32_t STG = 36864;
    const uint32_t MB_FULL = 110592, MB_EMPTY = 110616;

    int tid = threadIdx.x, lane = tid & 31;
    int gid = lane >> 2, tig = lane & 3;
    int wid = tid >> 5, wm = wid >> 2, wn = wid & 3;

    if (tid < 3) {
        MBAR_INIT(su + MB_FULL + tid * 8, 256);
        MBAR_INIT(su + MB_EMPTY + tid * 8, 256);
    }

    const __half* asrc[4]; uint32_t asz[4], adst[4];
#pragma unroll
    for (int j = 0; j < 4; j++) {
        int idx = tid + j * 256;
        int row = idx >> 3, c = idx & 7;
        int r = base + row;
        bool v = r < cnt;
        size_t arow = v ? (size_t)(off + r) : 0;
        asrc[j] = g_h16 + arow * FDIM + kbase + c * 8;
        asz[j] = v ? 16u : 0u;
        adst[j] = (uint32_t)(row * 144 + c * 16);
    }
    const __half* bsrc[4]; uint32_t bdst[4];
#pragma unroll
    for (int j = 0; j < 4; j++) {
        int idx = tid + j * 256;
        int n = idx >> 3, c = idx & 7;
        bsrc[j] = wde + (size_t)(n0 + n) * FDIM + kbase + c * 8;
        bdst[j] = (uint32_t)(n * 144 + c * 16);
    }

    uint32_t aoff[4];
#pragma unroll
    for (int m = 0; m < 4; m++)
        aoff[m] = (uint32_t)(((wm * 64 + m * 16 + (lane & 15)) * 72 + (lane >> 4) * 8) * 2);
    uint32_t boff[2];
#pragma unroll
    for (int p = 0; p < 2; p++)
        boff[p] = (uint32_t)(((wn * 32 + p * 16 + (lane & 7) + ((lane >> 4) & 1) * 8) * 72 +
                              ((lane >> 3) & 1) * 8) * 2);

    float acc[4][4][4];
#pragma unroll
    for (int m = 0; m < 4; m++)
#pragma unroll
        for (int n = 0; n < 4; n++)
#pragma unroll
            for (int q = 0; q < 4; q++) acc[m][n][q] = 0.f;

    const int KI = FDIM / 128;  // 32 tiles per split

#define DN_CP(s, k0)                                                     \
    do {                                                                 \
        uint32_t abw = su + (uint32_t)(s) * STG;                         \
        _Pragma("unroll") for (int j = 0; j < 4; j++)                    \
            CP16(abw + adst[j], asrc[j] + (k0), asz[j]);                 \
        _Pragma("unroll") for (int j = 0; j < 4; j++)                    \
            CP16(abw + 18432u + bdst[j], bsrc[j] + (k0), 16u);           \
    } while (0)

#define DN_STEP(kb)                                                      \
    do {                                                                 \
        uint32_t af[4][4], bf[2][4];                                     \
        LDSM4(bf[0][0], bf[0][1], bf[0][2], bf[0][3], ab + 18432u + boff[0] + (kb)); \
        LDSM4(af[0][0], af[0][1], af[0][2], af[0][3], ab + aoff[0] + (kb)); \
        LDSM4(bf[1][0], bf[1][1], bf[1][2], bf[1][3], ab + 18432u + boff[1] + (kb)); \
        LDSM4(af[1][0], af[1][1], af[1][2], af[1][3], ab + aoff[1] + (kb)); \
        mma16(acc[0][0], af[0], bf[0] + 0);                              \
        mma16(acc[0][1], af[0], bf[0] + 2);                              \
        mma16(acc[0][2], af[0], bf[1] + 0);                              \
        mma16(acc[0][3], af[0], bf[1] + 2);                              \
        LDSM4(af[2][0], af[2][1], af[2][2], af[2][3], ab + aoff[2] + (kb)); \
        mma16(acc[1][0], af[1], bf[0] + 0);                              \
        mma16(acc[1][1], af[1], bf[0] + 2);                              \
        mma16(acc[1][2], af[1], bf[1] + 0);                              \
        mma16(acc[1][3], af[1], bf[1] + 2);                              \
        LDSM4(af[3][0], af[3][1], af[3][2], af[3][3], ab + aoff[3] + (kb)); \
        mma16(acc[2][0], af[2], bf[0] + 0);                              \
        mma16(acc[2][1], af[2], bf[0] + 2);                              \
        mma16(acc[2][2], af[2], bf[1] + 0);                              \
        mma16(acc[2][3], af[2], bf[1] + 2);                              \
        mma16(acc[3][0], af[3], bf[0] + 0);                              \
        mma16(acc[3][1], af[3], bf[0] + 2);                              \
        mma16(acc[3][2], af[3], bf[1] + 0);                              \
        mma16(acc[3][3], af[3], bf[1] + 2);                              \
    } while (0)

    __syncthreads();  // barrier init visible before any async arrive targets them

    DN_CP(0, 0);  CPASYNC_MBAR_ARRIVE(su + MB_FULL + 0 * 8);
    DN_CP(1, 64); CPASYNC_MBAR_ARRIVE(su + MB_FULL + 1 * 8);

    int phF0 = 0, phF1 = 0, phF2 = 0;
    int phE0 = 0, phE1 = 0, phE2 = 0;
    int sC = 0, sP = 2;
    for (int i = 0; i < KI; i++) {
        int s = sC;
        sC = (sC == 2) ? 0 : sC + 1;
        int ph = (s == 0) ? phF0 : (s == 1) ? phF1 : phF2;
        MBAR_WAIT(su + MB_FULL + s * 8, ph);
        if (s == 0) phF0 ^= 1; else if (s == 1) phF1 ^= 1; else phF2 ^= 1;
        uint32_t ab = su + (uint32_t)s * STG;
        DN_STEP(0);
        if (i + 2 < KI) {
            int sc = sP;
            sP = (sP == 2) ? 0 : sP + 1;
            if (i > 0) {
                int pe = (sc == 0) ? phE0 : (sc == 1) ? phE1 : phE2;
                MBAR_WAIT(su + MB_EMPTY + sc * 8, pe);
                if (sc == 0) phE0 ^= 1; else if (sc == 1) phE1 ^= 1; else phE2 ^= 1;
            }
            DN_CP(sc, (i + 2) * 64);
            CPASYNC_MBAR_ARRIVE(su + MB_FULL + sc * 8);
        }
        DN_STEP(32);
        DN_STEP(64);
        DN_STEP(96);
        MBAR_ARRIVE(su + MB_EMPTY + s * 8);
    }
#undef DN_CP
#undef DN_STEP

    // epilogue: weighted scatter into buffer (split*2 + slot)
#pragma unroll
    for (int m = 0; m < 4; m++) {
#pragma unroll
        for (int half = 0; half < 2; half++) {
            int R = wm * 64 + m * 16 + gid + half * 8;
            int r = base + R;
            if (r >= cnt) continue;
            int t = g_tok[e * TOKS + r];
            int sl = g_slot[e * TOKS + r];
            float w = g_wt[e * TOKS + r];
            size_t yb = ((size_t)(split * 2 + sl) * TOKS + t) * HDIM + n0;
#pragma unroll
            for (int n = 0; n < 4; n++) {
                int col = wn * 32 + n * 8 + 2 * tig;
                float v0 = acc[m][n][half * 2 + 0], v1 = acc[m][n][half * 2 + 1];
                *reinterpret_cast<float2*>(g_y + yb + col) = make_float2(w * v0, w * v1);
            }
        }
    }
}

// ---------------- combine: out = sum of 4 split/slot buffers ----------------
__global__ void moe_combine(float* __restrict__ out) {
    size_t i = (size_t)blockIdx.x * 256 + threadIdx.x;
    const float4* y0 = reinterpret_cast<const float4*>(g_y);
    const size_t stride = (size_t)TOKS * HDIM / 4;
    float4 a = y0[i], b = y0[i + stride], c = y0[i + 2 * stride], d = y0[i + 3 * stride];
    reinterpret_cast<float4*>(out)[i] =
        make_float4(a.x + b.x + c.x + d.x, a.y + b.y + c.y + d.y,
                    a.z + b.z + c.z + d.z, a.w + b.w + c.w + d.w);
}

// ---------------- launch ----------------
extern "C" void kernel_launch(void* const* d_in, const int* in_sizes, int n_in,
                              void* d_out, int out_size) {
    const float* x   = (const float*)d_in[0];
    const float* wg  = (const float*)d_in[1];
    const float* wgp = (const float*)d_in[2];
    const float* wup = (const float*)d_in[3];
    const float* wdp = (const float*)d_in[4];
    float* out = (float*)d_out;

    cudaFuncSetAttribute(moe_gateup, cudaFuncAttributeMaxDynamicSharedMemorySize, 110640);
    cudaFuncSetAttribute(moe_down,   cudaFuncAttributeMaxDynamicSharedMemorySize, 110640);

    conv_x<<<(TOKS * HDIM / 8) / 256, 256>>>(x);                          // #0 (+ zero g_cnt)
    conv_w3<<<dim3(64, 16, 24), 256>>>(wgp, wup, wdp);                    // #1
    moe_router<<<TOKS / 8, 256>>>(x, wg, out + (size_t)TOKS * HDIM);      // #2
    moe_gateup<<<dim3(FDIM / 64, 20, NEXP), 256, 110640>>>();             // #3 (mbarrier ring)
    moe_down<<<dim3(HDIM / 128, 20, NEXP * 2), 256, 110640>>>();          // #4 (ring + split-K)
    moe_combine<<<(TOKS * HDIM / 4) / 256, 256>>>(out);                   // #5
}

// round 17
// speedup vs baseline: 1.3013x; 1.0098x over previous
#include <cuda_runtime.h>
#include <cuda_fp16.h>
#include <cstdint>

#define TOKS 8192
#define HDIM 1024
#define FDIM 4096
#define NEXP 8

// ---------------- scratch (__device__ globals; no allocation) ----------------
__device__ int    g_cnt[NEXP];
__device__ int    g_tok[NEXP * TOKS];
__device__ int    g_slot[NEXP * TOKS];
__device__ float  g_wt[NEXP * TOKS];
__device__ __half g_x16[(size_t)TOKS * HDIM];            // fp16 x (16 MB)
__device__ __half g_wg16[(size_t)NEXP * FDIM * HDIM];    // gate W, [e][n][k] (64 MB)
__device__ __half g_wu16[(size_t)NEXP * FDIM * HDIM];    // up   W, [e][n][k] (64 MB)
__device__ __half g_wd16[(size_t)NEXP * HDIM * FDIM];    // down W, [e][n][k] (64 MB)
__device__ __half g_h16[(size_t)2 * TOKS * FDIM];        // hidden (128 MB)
__device__ float  g_y[(size_t)4 * TOKS * HDIM];          // [split][slot] outputs (128 MB)

// ---------------- helpers ----------------
static __device__ __forceinline__ uint32_t smem_u32(const void* p) {
    uint32_t a;
    asm("{ .reg .u64 t; cvta.to.shared.u64 t, %1; cvt.u32.u64 %0, t; }" : "=r"(a) : "l"(p));
    return a;
}
static __device__ __forceinline__ void mma16(float* c, const uint32_t* a, const uint32_t* b) {
    asm volatile(
        "mma.sync.aligned.m16n8k16.row.col.f32.f16.f16.f32 "
        "{%0,%1,%2,%3}, {%4,%5,%6,%7}, {%8,%9}, {%0,%1,%2,%3};"
        : "+f"(c[0]), "+f"(c[1]), "+f"(c[2]), "+f"(c[3])
        : "r"(a[0]), "r"(a[1]), "r"(a[2]), "r"(a[3]), "r"(b[0]), "r"(b[1]));
}
#define LDSM4(r0, r1, r2, r3, addr)                                              \
    asm volatile("ldmatrix.sync.aligned.m8n8.x4.shared.b16 {%0,%1,%2,%3}, [%4];" \
                 : "=r"(r0), "=r"(r1), "=r"(r2), "=r"(r3) : "r"(addr))
#define CP16(dst, src, sz) \
    asm volatile("cp.async.cg.shared.global [%0], [%1], 16, %2;\n" ::"r"(dst), "l"(src), "r"(sz))

// mbarrier ring (sm_80 baseline PTX)
#define MBAR_INIT(a, c) asm volatile("mbarrier.init.shared.b64 [%0], %1;" ::"r"(a), "r"(c) : "memory")
#define MBAR_ARRIVE(a)  asm volatile("mbarrier.arrive.shared.b64 _, [%0];" ::"r"(a) : "memory")
#define CPASYNC_MBAR_ARRIVE(a) \
    asm volatile("cp.async.mbarrier.arrive.noinc.shared.b64 [%0];" ::"r"(a) : "memory")
#define MBAR_WAIT(mbar, parity) do {                                                   \
    uint32_t _m = (uint32_t)(mbar);                                                    \
    uint32_t _p = (uint32_t)(parity);                                                  \
    uint32_t _done;                                                                    \
    asm volatile(                                                                      \
        "{\n\t.reg .pred p;\n\t"                                                       \
        "mbarrier.try_wait.parity.shared.b64 p, [%1], %2;\n\t"                         \
        "selp.b32 %0, 1, 0, p;\n\t}"                                                   \
        : "=r"(_done) : "r"(_m), "r"(_p) : "memory");                                  \
    if (!_done) {                                                                      \
        asm volatile(                                                                  \
            "{\n\t.reg .pred P1;\n\t"                                                  \
            "WAIT_LOOP_%=:\n\t"                                                        \
            "mbarrier.try_wait.parity.shared.b64 P1, [%0], %1;\n\t"                    \
            "@P1 bra.uni WAIT_DONE_%=;\n\t"                                            \
            "bra.uni WAIT_LOOP_%=;\n\t"                                                \
            "WAIT_DONE_%=:\n\t}"                                                       \
            :: "r"(_m), "r"(_p) : "memory");                                           \
    }                                                                                  \
} while (0)

static __device__ __forceinline__ float silu(float v) { return v / (1.f + __expf(-v)); }

static __device__ __forceinline__ int expert_off(int e) {
    int off = 0;
#pragma unroll
    for (int i = 0; i < NEXP; i++) if (i < e) off += g_cnt[i];
    return off;
}

// ---------------- convert x -> fp16 (also zeroes g_cnt) ----------------
__global__ void conv_x(const float* __restrict__ x) {
    if (blockIdx.x == 0 && threadIdx.x < NEXP) g_cnt[threadIdx.x] = 0;
    size_t i = ((size_t)blockIdx.x * 256 + threadIdx.x) * 8;
    float4 a = *reinterpret_cast<const float4*>(x + i);
    float4 b = *reinterpret_cast<const float4*>(x + i + 4);
    __half2 h[4];
    h[0] = __floats2half2_rn(a.x, a.y);
    h[1] = __floats2half2_rn(a.z, a.w);
    h[2] = __floats2half2_rn(b.x, b.y);
    h[3] = __floats2half2_rn(b.z, b.w);
    *reinterpret_cast<uint4*>(g_x16 + i) = *reinterpret_cast<uint4*>(h);
}

// ---------------- convert+transpose gate+up W: [e][k][n] fp32 -> [e][n][k] fp16 ----------------
// grid (64, 16, 16): e = z&7, set = z>>3 (0=gate, 1=up); k0 = y*64, n0 = x*64.
__global__ void conv_wgu(const float* __restrict__ wgp, const float* __restrict__ wup) {
    __shared__ float t[64][65];
    int set = blockIdx.z >> 3, e = blockIdx.z & 7;
    const float* src = set ? wup : wgp;
    __half* dst = set ? g_wu16 : g_wg16;
    const int Kd = HDIM, Nd = FDIM;
    int k0 = blockIdx.y * 64, n0 = blockIdx.x * 64;

    const float* S = src + ((size_t)e * Kd + k0) * Nd + n0;
    int tid = threadIdx.x;
    int kr = tid >> 4, nc = (tid & 15) * 4;
#pragma unroll
    for (int j = 0; j < 4; j++) {
        float4 v = *reinterpret_cast<const float4*>(S + (size_t)(kr + j * 16) * Nd + nc);
        t[kr + j * 16][nc + 0] = v.x;
        t[kr + j * 16][nc + 1] = v.y;
        t[kr + j * 16][nc + 2] = v.z;
        t[kr + j * 16][nc + 3] = v.w;
    }
    __syncthreads();
    int nr = tid >> 2, kc = (tid & 3) * 16;
    __half hb[16];
#pragma unroll
    for (int q = 0; q < 16; q++) hb[q] = __float2half_rn(t[kc + q][nr]);
    __half* D = dst + ((size_t)e * Nd + n0 + nr) * Kd + k0 + kc;
    *reinterpret_cast<uint4*>(D)     = *reinterpret_cast<uint4*>(hb);
    *reinterpret_cast<uint4*>(D + 8) = *reinterpret_cast<uint4*>(hb + 8);
}

// ---------------- convert+transpose down W: grid (64, 16, 8); k0 = x*64, n0 = y*64 ----------------
__global__ void conv_wd(const float* __restrict__ wdp) {
    __shared__ float t[64][65];
    int e = blockIdx.z;
    const int Kd = FDIM, Nd = HDIM;
    int k0 = blockIdx.x * 64, n0 = blockIdx.y * 64;

    const float* S = wdp + ((size_t)e * Kd + k0) * Nd + n0;
    int tid = threadIdx.x;
    int kr = tid >> 4, nc = (tid & 15) * 4;
#pragma unroll
    for (int j = 0; j < 4; j++) {
        float4 v = *reinterpret_cast<const float4*>(S + (size_t)(kr + j * 16) * Nd + nc);
        t[kr + j * 16][nc + 0] = v.x;
        t[kr + j * 16][nc + 1] = v.y;
        t[kr + j * 16][nc + 2] = v.z;
        t[kr + j * 16][nc + 3] = v.w;
    }
    __syncthreads();
    int nr = tid >> 2, kc = (tid & 3) * 16;
    __half hb[16];
#pragma unroll
    for (int q = 0; q < 16; q++) hb[q] = __float2half_rn(t[kc + q][nr]);
    __half* D = g_wd16 + ((size_t)e * Nd + n0 + nr) * Kd + k0 + kc;
    *reinterpret_cast<uint4*>(D)     = *reinterpret_cast<uint4*>(hb);
    *reinterpret_cast<uint4*>(D + 8) = *reinterpret_cast<uint4*>(hb + 8);
}

// ---------------- router ----------------
__global__ void moe_router(const float* __restrict__ x, const float* __restrict__ wg,
                           float* __restrict__ logits_out) {
    int t = blockIdx.x * 8 + (threadIdx.x >> 5);
    int lane = threadIdx.x & 31;
    const float* xr = x + (size_t)t * HDIM;
    float acc[8] = {0.f, 0.f, 0.f, 0.f, 0.f, 0.f, 0.f, 0.f};
    for (int j = lane; j < HDIM; j += 32) {
        float xv = xr[j];
        const float4* w4 = reinterpret_cast<const float4*>(wg + (size_t)j * NEXP);
        float4 a = w4[0], b = w4[1];
        acc[0] += xv * a.x; acc[1] += xv * a.y; acc[2] += xv * a.z; acc[3] += xv * a.w;
        acc[4] += xv * b.x; acc[5] += xv * b.y; acc[6] += xv * b.z; acc[7] += xv * b.w;
    }
#pragma unroll
    for (int o = 16; o > 0; o >>= 1)
#pragma unroll
        for (int k = 0; k < 8; k++) acc[k] += __shfl_xor_sync(0xffffffffu, acc[k], o);

    if (lane == 0) {
#pragma unroll
        for (int k = 0; k < 8; k++) logits_out[(size_t)t * NEXP + k] = acc[k];
        int i0 = 0; float v0 = acc[0];
#pragma unroll
        for (int k = 1; k < 8; k++) if (acc[k] > v0) { v0 = acc[k]; i0 = k; }
        int i1 = -1; float v1 = -3.4e38f;
#pragma unroll
        for (int k = 0; k < 8; k++) if (k != i0 && acc[k] > v1) { v1 = acc[k]; i1 = k; }
        float w0 = 1.f / (1.f + __expf(v1 - v0));
        float w1 = 1.f - w0;
        int p0 = atomicAdd(&g_cnt[i0], 1);
        g_tok[i0 * TOKS + p0] = t; g_slot[i0 * TOKS + p0] = 0; g_wt[i0 * TOKS + p0] = w0;
        int p1 = atomicAdd(&g_cnt[i1], 1);
        g_tok[i1 * TOKS + p1] = t; g_slot[i1 * TOKS + p1] = 1; g_wt[i1 * TOKS + p1] = w1;
    }
}

// ---------------- fused gate+up GEMM: mbarrier producer/consumer ring ----------------
__global__ void __launch_bounds__(256, 2)
moe_gateup() {
    int e = blockIdx.z;
    int cnt = g_cnt[e];
    int base = blockIdx.y * 128;
    if (base >= cnt) return;
    int n0 = blockIdx.x * 64;
    int off = expert_off(e);
    const __half* wge = g_wg16 + (size_t)e * FDIM * HDIM;
    const __half* wue = g_wu16 + (size_t)e * FDIM * HDIM;

    extern __shared__ char smem8[];
    uint32_t su = smem_u32(smem8);
    const uint32_t STG = 36864;
    const uint32_t MB_FULL = 110592, MB_EMPTY = 110616;

    int tid = threadIdx.x, lane = tid & 31;
    int gid = lane >> 2, tig = lane & 3;
    int wid = tid >> 5, wm = wid >> 2, wn = wid & 3;

    if (tid < 3) {
        MBAR_INIT(su + MB_FULL + tid * 8, 256);
        MBAR_INIT(su + MB_EMPTY + tid * 8, 256);
    }

    const __half* asrc[4]; uint32_t asz[4], adst[4];
#pragma unroll
    for (int j = 0; j < 4; j++) {
        int idx = tid + j * 256;
        int row = idx >> 3, c = idx & 7;
        int r = base + row;
        bool v = r < cnt;
        int tok = v ? g_tok[e * TOKS + r] : 0;
        asrc[j] = g_x16 + (size_t)tok * HDIM + c * 8;
        asz[j] = v ? 16u : 0u;
        adst[j] = (uint32_t)(row * 144 + c * 16);
    }
    const __half* gsrc[2]; const __half* usrc[2]; uint32_t bdst[2];
#pragma unroll
    for (int j = 0; j < 2; j++) {
        int idx = tid + j * 256;
        int n = idx >> 3, c = idx & 7;
        gsrc[j] = wge + (size_t)(n0 + n) * HDIM + c * 8;
        usrc[j] = wue + (size_t)(n0 + n) * HDIM + c * 8;
        bdst[j] = (uint32_t)(n * 144 + c * 16);
    }

    uint32_t aoff[4];
#pragma unroll
    for (int m = 0; m < 4; m++)
        aoff[m] = (uint32_t)(((wm * 64 + m * 16 + (lane & 15)) * 72 + (lane >> 4) * 8) * 2);
    uint32_t boff = (uint32_t)(((wn * 16 + (lane & 7) + ((lane >> 4) & 1) * 8) * 72 +
                                ((lane >> 3) & 1) * 8) * 2);

    float accG[4][2][4], accU[4][2][4];
#pragma unroll
    for (int m = 0; m < 4; m++)
#pragma unroll
        for (int n = 0; n < 2; n++)
#pragma unroll
            for (int q = 0; q < 4; q++) { accG[m][n][q] = 0.f; accU[m][n][q] = 0.f; }

    const int KI = HDIM / 64;  // 16

#define GU_CP(s, k0)                                                     \
    do {                                                                 \
        uint32_t abw = su + (uint32_t)(s) * STG;                         \
        _Pragma("unroll") for (int j = 0; j < 4; j++)                    \
            CP16(abw + adst[j], asrc[j] + (k0), asz[j]);                 \
        _Pragma("unroll") for (int j = 0; j < 2; j++)                    \
            CP16(abw + 18432u + bdst[j], gsrc[j] + (k0), 16u);           \
        _Pragma("unroll") for (int j = 0; j < 2; j++)                    \
            CP16(abw + 27648u + bdst[j], usrc[j] + (k0), 16u);           \
    } while (0)

#define GU_STEP(kb)                                                      \
    do {                                                                 \
        uint32_t af[4][4], bg[4], bu[4];                                 \
        LDSM4(bg[0], bg[1], bg[2], bg[3], ab + 18432u + boff + (kb));    \
        LDSM4(af[0][0], af[0][1], af[0][2], af[0][3], ab + aoff[0] + (kb)); \
        LDSM4(bu[0], bu[1], bu[2], bu[3], ab + 27648u + boff + (kb));    \
        LDSM4(af[1][0], af[1][1], af[1][2], af[1][3], ab + aoff[1] + (kb)); \
        mma16(accG[0][0], af[0], bg + 0);                                \
        mma16(accG[0][1], af[0], bg + 2);                                \
        mma16(accU[0][0], af[0], bu + 0);                                \
        mma16(accU[0][1], af[0], bu + 2);                                \
        LDSM4(af[2][0], af[2][1], af[2][2], af[2][3], ab + aoff[2] + (kb)); \
        mma16(accG[1][0], af[1], bg + 0);                                \
        mma16(accG[1][1], af[1], bg + 2);                                \
        mma16(accU[1][0], af[1], bu + 0);                                \
        mma16(accU[1][1], af[1], bu + 2);                                \
        LDSM4(af[3][0], af[3][1], af[3][2], af[3][3], ab + aoff[3] + (kb)); \
        mma16(accG[2][0], af[2], bg + 0);                                \
        mma16(accG[2][1], af[2], bg + 2);                                \
        mma16(accU[2][0], af[2], bu + 0);                                \
        mma16(accU[2][1], af[2], bu + 2);                                \
        mma16(accG[3][0], af[3], bg + 0);                                \
        mma16(accG[3][1], af[3], bg + 2);                                \
        mma16(accU[3][0], af[3], bu + 0);                                \
        mma16(accU[3][1], af[3], bu + 2);                                \
    } while (0)

    __syncthreads();  // barrier init visible before any async arrive targets them

    GU_CP(0, 0);  CPASYNC_MBAR_ARRIVE(su + MB_FULL + 0 * 8);
    GU_CP(1, 64); CPASYNC_MBAR_ARRIVE(su + MB_FULL + 1 * 8);

    int phF0 = 0, phF1 = 0, phF2 = 0;
    int phE0 = 0, phE1 = 0, phE2 = 0;
    int sC = 0, sP = 2;
    for (int i = 0; i < KI; i++) {
        int s = sC;
        sC = (sC == 2) ? 0 : sC + 1;
        int ph = (s == 0) ? phF0 : (s == 1) ? phF1 : phF2;
        MBAR_WAIT(su + MB_FULL + s * 8, ph);
        if (s == 0) phF0 ^= 1; else if (s == 1) phF1 ^= 1; else phF2 ^= 1;
        uint32_t ab = su + (uint32_t)s * STG;
        GU_STEP(0);
        if (i + 2 < KI) {
            int sc = sP;
            sP = (sP == 2) ? 0 : sP + 1;
            if (i > 0) {
                int pe = (sc == 0) ? phE0 : (sc == 1) ? phE1 : phE2;
                MBAR_WAIT(su + MB_EMPTY + sc * 8, pe);
                if (sc == 0) phE0 ^= 1; else if (sc == 1) phE1 ^= 1; else phE2 ^= 1;
            }
            GU_CP(sc, (i + 2) * 64);
            CPASYNC_MBAR_ARRIVE(su + MB_FULL + sc * 8);
        }
        GU_STEP(32);
        GU_STEP(64);
        GU_STEP(96);
        MBAR_ARRIVE(su + MB_EMPTY + s * 8);
    }
#undef GU_CP
#undef GU_STEP

    // epilogue: g_h16 = fp16(silu(g) * u)
#pragma unroll
    for (int m = 0; m < 4; m++) {
#pragma unroll
        for (int half = 0; half < 2; half++) {
            int R = wm * 64 + m * 16 + gid + half * 8;
            int r = base + R;
            if (r >= cnt) continue;
            size_t rb = (size_t)(off + r) * FDIM + n0;
#pragma unroll
            for (int n = 0; n < 2; n++) {
                int col = wn * 16 + n * 8 + 2 * tig;
                float h0 = silu(accG[m][n][half * 2 + 0]) * accU[m][n][half * 2 + 0];
                float h1 = silu(accG[m][n][half * 2 + 1]) * accU[m][n][half * 2 + 1];
                *reinterpret_cast<__half2*>(g_h16 + rb + col) = __floats2half2_rn(h0, h1);
            }
        }
    }
}

// ---------------- down GEMM, split-K=2, mbarrier ring ----------------
__global__ void __launch_bounds__(256, 2)
moe_down() {
    int e = blockIdx.z & 7;
    int split = blockIdx.z >> 3;
    int cnt = g_cnt[e];
    int base = blockIdx.y * 128;
    if (base >= cnt) return;
    int n0 = blockIdx.x * 128;
    int off = expert_off(e);
    int kbase = split * (FDIM / 2);
    const __half* wde = g_wd16 + (size_t)e * HDIM * FDIM;

    extern __shared__ char smem8[];
    uint32_t su = smem_u32(smem8);
    const uint32_t STG = 36864;
    const uint32_t MB_FULL = 110592, MB_EMPTY = 110616;

    int tid = threadIdx.x, lane = tid & 31;
    int gid = lane >> 2, tig = lane & 3;
    int wid = tid >> 5, wm = wid >> 2, wn = wid & 3;

    if (tid < 3) {
        MBAR_INIT(su + MB_FULL + tid * 8, 256);
        MBAR_INIT(su + MB_EMPTY + tid * 8, 256);
    }

    const __half* asrc[4]; uint32_t asz[4], adst[4];
#pragma unroll
    for (int j = 0; j < 4; j++) {
        int idx = tid + j * 256;
        int row = idx >> 3, c = idx & 7;
        int r = base + row;
        bool v = r < cnt;
        size_t arow = v ? (size_t)(off + r) : 0;
        asrc[j] = g_h16 + arow * FDIM + kbase + c * 8;
        asz[j] = v ? 16u : 0u;
        adst[j] = (uint32_t)(row * 144 + c * 16);
    }
    const __half* bsrc[4]; uint32_t bdst[4];
#pragma unroll
    for (int j = 0; j < 4; j++) {
        int idx = tid + j * 256;
        int n = idx >> 3, c = idx & 7;
        bsrc[j] = wde + (size_t)(n0 + n) * FDIM + kbase + c * 8;
        bdst[j] = (uint32_t)(n * 144 + c * 16);
    }

    uint32_t aoff[4];
#pragma unroll
    for (int m = 0; m < 4; m++)
        aoff[m] = (uint32_t)(((wm * 64 + m * 16 + (lane & 15)) * 72 + (lane >> 4) * 8) * 2);
    uint32_t boff[2];
#pragma unroll
    for (int p = 0; p < 2; p++)
        boff[p] = (uint32_t)(((wn * 32 + p * 16 + (lane & 7) + ((lane >> 4) & 1) * 8) * 72 +
                              ((lane >> 3) & 1) * 8) * 2);

    float acc[4][4][4];
#pragma unroll
    for (int m = 0; m < 4; m++)
#pragma unroll
        for (int n = 0; n < 4; n++)
#pragma unroll
            for (int q = 0; q < 4; q++) acc[m][n][q] = 0.f;

    const int KI = FDIM / 128;  // 32 tiles per split

#define DN_CP(s, k0)                                                     \
    do {                                                                 \
        uint32_t abw = su + (uint32_t)(s) * STG;                         \
        _Pragma("unroll") for (int j = 0; j < 4; j++)                    \
            CP16(abw + adst[j], asrc[j] + (k0), asz[j]);                 \
        _Pragma("unroll") for (int j = 0; j < 4; j++)                    \
            CP16(abw + 18432u + bdst[j], bsrc[j] + (k0), 16u);           \
    } while (0)

#define DN_STEP(kb)                                                      \
    do {                                                                 \
        uint32_t af[4][4], bf[2][4];                                     \
        LDSM4(bf[0][0], bf[0][1], bf[0][2], bf[0][3], ab + 18432u + boff[0] + (kb)); \
        LDSM4(af[0][0], af[0][1], af[0][2], af[0][3], ab + aoff[0] + (kb)); \
        LDSM4(bf[1][0], bf[1][1], bf[1][2], bf[1][3], ab + 18432u + boff[1] + (kb)); \
        LDSM4(af[1][0], af[1][1], af[1][2], af[1][3], ab + aoff[1] + (kb)); \
        mma16(acc[0][0], af[0], bf[0] + 0);                              \
        mma16(acc[0][1], af[0], bf[0] + 2);                              \
        mma16(acc[0][2], af[0], bf[1] + 0);                              \
        mma16(acc[0][3], af[0], bf[1] + 2);                              \
        LDSM4(af[2][0], af[2][1], af[2][2], af[2][3], ab + aoff[2] + (kb)); \
        mma16(acc[1][0], af[1], bf[0] + 0);                              \
        mma16(acc[1][1], af[1], bf[0] + 2);                              \
        mma16(acc[1][2], af[1], bf[1] + 0);                              \
        mma16(acc[1][3], af[1], bf[1] + 2);                              \
        LDSM4(af[3][0], af[3][1], af[3][2], af[3][3], ab + aoff[3] + (kb)); \
        mma16(acc[2][0], af[2], bf[0] + 0);                              \
        mma16(acc[2][1], af[2], bf[0] + 2);                              \
        mma16(acc[2][2], af[2], bf[1] + 0);                              \
        mma16(acc[2][3], af[2], bf[1] + 2);                              \
        mma16(acc[3][0], af[3], bf[0] + 0);                              \
        mma16(acc[3][1], af[3], bf[0] + 2);                              \
        mma16(acc[3][2], af[3], bf[1] + 0);                              \
        mma16(acc[3][3], af[3], bf[1] + 2);                              \
    } while (0)

    __syncthreads();  // barrier init visible before any async arrive targets them

    DN_CP(0, 0);  CPASYNC_MBAR_ARRIVE(su + MB_FULL + 0 * 8);
    DN_CP(1, 64); CPASYNC_MBAR_ARRIVE(su + MB_FULL + 1 * 8);

    int phF0 = 0, phF1 = 0, phF2 = 0;
    int phE0 = 0, phE1 = 0, phE2 = 0;
    int sC = 0, sP = 2;
    for (int i = 0; i < KI; i++) {
        int s = sC;
        sC = (sC == 2) ? 0 : sC + 1;
        int ph = (s == 0) ? phF0 : (s == 1) ? phF1 : phF2;
        MBAR_WAIT(su + MB_FULL + s * 8, ph);
        if (s == 0) phF0 ^= 1; else if (s == 1) phF1 ^= 1; else phF2 ^= 1;
        uint32_t ab = su + (uint32_t)s * STG;
        DN_STEP(0);
        if (i + 2 < KI) {
            int sc = sP;
            sP = (sP == 2) ? 0 : sP + 1;
            if (i > 0) {
                int pe = (sc == 0) ? phE0 : (sc == 1) ? phE1 : phE2;
                MBAR_WAIT(su + MB_EMPTY + sc * 8, pe);
                if (sc == 0) phE0 ^= 1; else if (sc == 1) phE1 ^= 1; else phE2 ^= 1;
            }
            DN_CP(sc, (i + 2) * 64);
            CPASYNC_MBAR_ARRIVE(su + MB_FULL + sc * 8);
        }
        DN_STEP(32);
        DN_STEP(64);
        DN_STEP(96);
        MBAR_ARRIVE(su + MB_EMPTY + s * 8);
    }
#undef DN_CP
#undef DN_STEP

    // epilogue: weighted scatter into buffer (split*2 + slot)
#pragma unroll
    for (int m = 0; m < 4; m++) {
#pragma unroll
        for (int half = 0; half < 2; half++) {
            int R = wm * 64 + m * 16 + gid + half * 8;
            int r = base + R;
            if (r >= cnt) continue;
            int t = g_tok[e * TOKS + r];
            int sl = g_slot[e * TOKS + r];
            float w = g_wt[e * TOKS + r];
            size_t yb = ((size_t)(split * 2 + sl) * TOKS + t) * HDIM + n0;
#pragma unroll
            for (int n = 0; n < 4; n++) {
                int col = wn * 32 + n * 8 + 2 * tig;
                float v0 = acc[m][n][half * 2 + 0], v1 = acc[m][n][half * 2 + 1];
                *reinterpret_cast<float2*>(g_y + yb + col) = make_float2(w * v0, w * v1);
            }
        }
    }
}

// ---------------- combine: out = sum of 4 split/slot buffers ----------------
__global__ void moe_combine(float* __restrict__ out) {
    size_t i = (size_t)blockIdx.x * 256 + threadIdx.x;
    const float4* y0 = reinterpret_cast<const float4*>(g_y);
    const size_t stride = (size_t)TOKS * HDIM / 4;
    float4 a = y0[i], b = y0[i + stride], c = y0[i + 2 * stride], d = y0[i + 3 * stride];
    reinterpret_cast<float4*>(out)[i] =
        make_float4(a.x + b.x + c.x + d.x, a.y + b.y + c.y + d.y,
                    a.z + b.z + c.z + d.z, a.w + b.w + c.w + d.w);
}

// ---------------- launch: fork conv_x/router/conv_wd onto a side stream ----------------
extern "C" void kernel_launch(void* const* d_in, const int* in_sizes, int n_in,
                              void* d_out, int out_size) {
    const float* x   = (const float*)d_in[0];
    const float* wg  = (const float*)d_in[1];
    const float* wgp = (const float*)d_in[2];
    const float* wup = (const float*)d_in[3];
    const float* wdp = (const float*)d_in[4];
    float* out = (float*)d_out;

    cudaFuncSetAttribute(moe_gateup, cudaFuncAttributeMaxDynamicSharedMemorySize, 110640);
    cudaFuncSetAttribute(moe_down,   cudaFuncAttributeMaxDynamicSharedMemorySize, 110640);

    // side stream + fork/join events (created per call; never destroyed — destroying
    // a stream participating in an active capture is illegal; leak is a few objects)
    cudaStream_t s1;
    cudaStreamCreateWithFlags(&s1, cudaStreamNonBlocking);
    cudaEvent_t evFork, evRoute, evWd;
    cudaEventCreateWithFlags(&evFork,  cudaEventDisableTiming);
    cudaEventCreateWithFlags(&evRoute, cudaEventDisableTiming);
    cudaEventCreateWithFlags(&evWd,    cudaEventDisableTiming);

    cudaEventRecord(evFork, 0);
    cudaStreamWaitEvent(s1, evFork, 0);

    // s1: x convert + router, then down-weight convert (hidden under gateup)
    conv_x<<<(TOKS * HDIM / 8) / 256, 256, 0, s1>>>(x);
    moe_router<<<TOKS / 8, 256, 0, s1>>>(x, wg, out + (size_t)TOKS * HDIM);
    cudaEventRecord(evRoute, s1);
    conv_wd<<<dim3(64, 16, NEXP), 256, 0, s1>>>(wdp);
    cudaEventRecord(evWd, s1);

    // main: gate/up weight convert in parallel with s1
    conv_wgu<<<dim3(64, 16, 16), 256>>>(wgp, wup);
    cudaStreamWaitEvent(0, evRoute, 0);
    moe_gateup<<<dim3(FDIM / 64, 20, NEXP), 256, 110640>>>();
    cudaStreamWaitEvent(0, evWd, 0);
    moe_down<<<dim3(HDIM / 128, 20, NEXP * 2), 256, 110640>>>();
    moe_combine<<<(TOKS * HDIM / 4) / 256, 256>>>(out);
}